// round 4
// baseline (speedup 1.0000x reference)
#include <cuda_runtime.h>
#include <math.h>

// ---------------------------------------------------------------------------
// Problem constants
// ---------------------------------------------------------------------------
#define NPOS 32768
#define CDIM 512
#define CK   256
#define HEADS 8
#define HK   32
#define BN_EPS 1e-5f

// ---------------------------------------------------------------------------
// Static device scratch (no allocation allowed)
// ---------------------------------------------------------------------------
__device__ float g_T   [2u * NPOS * 1280];   // per n: [keys(256) | queries(256) | values(256) | L1(512)]
__device__ float g_L2  [2u * NPOS * 256];    // adapt stage-2 output (BN folded)
__device__ float g_Q   [(size_t)NPOS * 512]; // softmaxed queries, cols = n*256 + head*32 + k
__device__ float g_Wbig[1280 * 512];         // concat weights for GEMM1 (BN folded on adapt1 rows)
__device__ float g_bias1[1280];
__device__ float g_W2  [256 * 512];          // BN-folded adapt_w2
__device__ float g_bias2[256];
__device__ float g_Wcat[512 * 512];          // 0.25 * wr @ blockdiag(ctx)  for both n
__device__ float g_brw [512];                // 0.5 * ea_br
__device__ float g_sum [1024];               // column sums of x,y (atomic)
__device__ float g_kmaxp[2 * 64 * 256];      // partial key maxes
__device__ float g_kmax[512];                // key max per (n, channel)
__device__ float g_ctx [2 * 8 * 32 * 32];    // ctx accumulators (atomic), normalized in prepB
__device__ float g_ksum[512];                // softmax denominators (atomic)
__device__ float g_high[512];                // high2 per n [2][256]
__device__ float g_Wd  [512];                // [Wdx(256) | Wdy(256)]  (delta path folded)
__device__ float g_cd  [4];                  // [cdx0, cdy0, cdx1, cdy1]
__device__ float g_wgt [2 * NPOS];           // grid_sample weight per (n, position)

// ---------------------------------------------------------------------------
// 0) zero accumulators
// ---------------------------------------------------------------------------
__global__ void k_zero() {
    int i = blockIdx.x * 256 + threadIdx.x;   // grid 64x256 = 16384
    g_ctx[i] = 0.f;
    if (i < 1024) g_sum[i] = 0.f;
    if (i < 512)  g_ksum[i] = 0.f;
}

// ---------------------------------------------------------------------------
// 1) prepA: build folded weight matrices & biases (independent of x,y)
// ---------------------------------------------------------------------------
__global__ void k_prepA(const float* __restrict__ ea_wk, const float* __restrict__ ea_bk,
                        const float* __restrict__ ea_wq, const float* __restrict__ ea_bq,
                        const float* __restrict__ ea_wv, const float* __restrict__ ea_bv,
                        const float* __restrict__ ea_br,
                        const float* __restrict__ adapt_w1, const float* __restrict__ adapt_bn1,
                        const float* __restrict__ adapt_w2, const float* __restrict__ adapt_bn2,
                        const float* __restrict__ delta_w1, const float* __restrict__ delta_bn1,
                        const float* __restrict__ delta_w2) {
    int b = blockIdx.x, t = threadIdx.x;   // 1537 blocks x 512 threads
    if (b < 1280) {
        int o = b;
        float scale = 1.f, bias = 0.f;
        const float* src;
        if (o < 256)       { src = ea_wk + o * 512;        bias = ea_bk[o]; }
        else if (o < 512)  { src = ea_wq + (o - 256) * 512; bias = ea_bq[o - 256]; }
        else if (o < 768)  { src = ea_wv + (o - 512) * 512; bias = ea_bv[o - 512]; }
        else {
            int oo = o - 768;
            float g = adapt_bn1[oo], be = adapt_bn1[512 + oo];
            float m = adapt_bn1[1024 + oo], v = adapt_bn1[1536 + oo];
            scale = g * rsqrtf(v + BN_EPS);
            bias  = be - m * scale;
            src   = adapt_w1 + oo * 512;
        }
        g_Wbig[o * 512 + t] = scale * src[t];
        if (t == 0) g_bias1[o] = bias;
    } else if (b < 1536) {
        int oo = b - 1280;
        float g = adapt_bn2[oo], be = adapt_bn2[256 + oo];
        float m = adapt_bn2[512 + oo], v = adapt_bn2[768 + oo];
        float scale = g * rsqrtf(v + BN_EPS);
        g_W2[oo * 512 + t] = scale * adapt_w2[oo * 512 + t];
        if (t == 0) g_bias2[oo] = be - m * scale;
    } else {
        g_brw[t] = 0.5f * ea_br[t];
        if (t < 256) {
            // Wdx[c] = sum_o dw2[0][o]*sd[o]*dw1[o][c]  (low half of delta_w1)
            float ax = 0.f, ay = 0.f;
            for (int o = 0; o < 256; o++) {
                float g = delta_bn1[o], v = delta_bn1[768 + o];
                float sd = g * rsqrtf(v + BN_EPS);
                float wv = delta_w1[o * 512 + t];
                ax = fmaf(delta_w2[o]       * sd, wv, ax);
                ay = fmaf(delta_w2[256 + o] * sd, wv, ay);
            }
            g_Wd[t] = ax;
            g_Wd[256 + t] = ay;
        }
    }
}

// ---------------------------------------------------------------------------
// 2) column sums of x and y (for AdaptiveAvgPool "high" path)
// ---------------------------------------------------------------------------
__global__ void k_colmean(const float* __restrict__ x, const float* __restrict__ y) {
    int n = blockIdx.y, t = threadIdx.x;          // grid (64,2) x 512
    const float* X = n ? y : x;
    int w0 = blockIdx.x * 512;
    float acc = 0.f;
    for (int r = 0; r < 512; r++)
        acc += X[(size_t)(w0 + r) * 512 + t];
    atomicAdd(&g_sum[n * 512 + t], acc);
}

// ---------------------------------------------------------------------------
// SGEMM core: C[MxNout] = A[Mx512] @ W[Noutx512]^T, 128x128x8 tile, 8x8/thread
// MODE 0: C = acc + bias[col]
// MODE 1: final fused epilogue -> out
// ---------------------------------------------------------------------------
template <int MODE>
__device__ __forceinline__ void gemm_core(
    const float* __restrict__ A, int lda,
    const float* __restrict__ W,
    const float* __restrict__ bias,
    float* __restrict__ C, int ldc,
    const float* __restrict__ xx, const float* __restrict__ yy) {

    __shared__ float As[8][132];
    __shared__ float Bs[8][132];

    const int tid  = threadIdx.x;
    const int tx   = tid & 15, ty = tid >> 4;
    const int m0   = blockIdx.y * 128;
    const int n0   = blockIdx.x * 128;
    const int arow = tid >> 1;
    const int acol = (tid & 1) * 4;

    const float* Ap = A + (size_t)(m0 + arow) * lda + acol;
    const float* Wp = W + (size_t)(n0 + arow) * 512 + acol;

    float acc[8][8];
#pragma unroll
    for (int i = 0; i < 8; i++)
#pragma unroll
        for (int j = 0; j < 8; j++) acc[i][j] = 0.f;

    for (int kt = 0; kt < 512; kt += 8) {
        float4 a4 = *(const float4*)(Ap + kt);
        float4 b4 = *(const float4*)(Wp + kt);
        As[acol + 0][arow] = a4.x; As[acol + 1][arow] = a4.y;
        As[acol + 2][arow] = a4.z; As[acol + 3][arow] = a4.w;
        Bs[acol + 0][arow] = b4.x; Bs[acol + 1][arow] = b4.y;
        Bs[acol + 2][arow] = b4.z; Bs[acol + 3][arow] = b4.w;
        __syncthreads();
#pragma unroll
        for (int k = 0; k < 8; k++) {
            float af[8], bf[8];
            *(float4*)(af)     = *(const float4*)(&As[k][ty * 8]);
            *(float4*)(af + 4) = *(const float4*)(&As[k][ty * 8 + 4]);
            *(float4*)(bf)     = *(const float4*)(&Bs[k][tx * 8]);
            *(float4*)(bf + 4) = *(const float4*)(&Bs[k][tx * 8 + 4]);
#pragma unroll
            for (int i = 0; i < 8; i++)
#pragma unroll
                for (int j = 0; j < 8; j++)
                    acc[i][j] = fmaf(af[i], bf[j], acc[i][j]);
        }
        __syncthreads();
    }

#pragma unroll
    for (int i = 0; i < 8; i++) {
        int row = m0 + ty * 8 + i;
        float w0v = 0.f, w1v = 0.f;
        if (MODE == 1) { w0v = g_wgt[row]; w1v = g_wgt[NPOS + row]; }
#pragma unroll
        for (int j = 0; j < 8; j++) {
            int col = n0 + tx * 8 + j;
            float v = acc[i][j];
            if (MODE == 0) {
                C[(size_t)row * ldc + col] = v + bias[col];
            } else {
                v += g_brw[col] + 0.25f * (xx[(size_t)row * 512 + col] + yy[(size_t)row * 512 + col]);
                if (col < 256)
                    v += 0.25f * (g_high[col] * w0v + g_high[256 + col] * w1v);
                else
                    v += 0.25f * (g_L2[(size_t)row * 256 + (col - 256)] +
                                  g_L2[(size_t)(NPOS + row) * 256 + (col - 256)]);
                C[(size_t)row * 512 + col] = v;
            }
        }
    }
}

__global__ void __launch_bounds__(256) k_gemm1(const float* __restrict__ x, const float* __restrict__ y) {
    int n = blockIdx.z;
    gemm_core<0>(n ? y : x, 512, g_Wbig, g_bias1,
                 g_T + (size_t)n * NPOS * 1280, 1280, nullptr, nullptr);
}
__global__ void __launch_bounds__(256) k_gemm2() {
    int n = blockIdx.z;
    gemm_core<0>(g_T + (size_t)n * NPOS * 1280 + 768, 1280, g_W2, g_bias2,
                 g_L2 + (size_t)n * NPOS * 256, 256, nullptr, nullptr);
}
__global__ void __launch_bounds__(256) k_gemmF(const float* __restrict__ x, const float* __restrict__ y,
                                               float* __restrict__ out) {
    gemm_core<1>(g_Q, 512, g_Wcat, nullptr, out, 512, x, y);
}

// ---------------------------------------------------------------------------
// 3) key max over positions (two-stage)
// ---------------------------------------------------------------------------
__global__ void k_kmax_part() {
    int n = blockIdx.y, t = threadIdx.x;   // grid (64,2) x 256
    int w0 = blockIdx.x * 512;
    float m = -1e30f;
    for (int r = 0; r < 512; r++)
        m = fmaxf(m, g_T[(size_t)(n * NPOS + w0 + r) * 1280 + t]);
    g_kmaxp[(size_t)(n * 64 + blockIdx.x) * 256 + t] = m;
}
__global__ void k_kmax_red() {
    int n = blockIdx.x, t = threadIdx.x;
    float m = -1e30f;
    for (int ch = 0; ch < 64; ch++)
        m = fmaxf(m, g_kmaxp[(size_t)(n * 64 + ch) * 256 + t]);
    g_kmax[n * 256 + t] = m;
}

// ---------------------------------------------------------------------------
// 4) ctx = sum_w exp(k - kmax) * v^T  (+ ksum), per (n, head)
// ---------------------------------------------------------------------------
__global__ void k_ctx() {
    int n = blockIdx.z, h = blockIdx.y;          // grid (16, 8, 2) x 256
    int w0 = blockIdx.x * 2048;
    int t = threadIdx.x;
    int p = t >> 5, i = t & 31;                  // loading role
    int ai = t >> 3, j0 = (t & 7) * 4;           // accumulation role
    float kmax = g_kmax[n * 256 + h * 32 + i];

    __shared__ float sE[8][33];
    __shared__ float sV[8][33];

    float acc0 = 0.f, acc1 = 0.f, acc2 = 0.f, acc3 = 0.f, ks = 0.f;

    for (int b = 0; b < 256; b++) {
        int w = w0 + b * 8 + p;
        size_t base = (size_t)(n * NPOS + w) * 1280;
        float e = __expf(g_T[base + h * 32 + i] - kmax);
        sE[p][i] = e;
        ks += e;
        sV[p][i] = g_T[base + 512 + h * 32 + i];
        __syncthreads();
#pragma unroll
        for (int pp = 0; pp < 8; pp++) {
            float ee = sE[pp][ai];
            acc0 = fmaf(ee, sV[pp][j0 + 0], acc0);
            acc1 = fmaf(ee, sV[pp][j0 + 1], acc1);
            acc2 = fmaf(ee, sV[pp][j0 + 2], acc2);
            acc3 = fmaf(ee, sV[pp][j0 + 3], acc3);
        }
        __syncthreads();
    }
    int base = ((n * 8 + h) * 32 + ai) * 32 + j0;
    atomicAdd(&g_ctx[base + 0], acc0);
    atomicAdd(&g_ctx[base + 1], acc1);
    atomicAdd(&g_ctx[base + 2], acc2);
    atomicAdd(&g_ctx[base + 3], acc3);
    atomicAdd(&g_ksum[n * 256 + h * 32 + i], ks);
}

// ---------------------------------------------------------------------------
// 5) query softmax over 32 head-channels (one warp = one head)
// ---------------------------------------------------------------------------
__global__ void k_qsm() {
    int w = blockIdx.x, n = blockIdx.y, t = threadIdx.x;   // grid (32768,2) x 256
    float q = g_T[(size_t)(n * NPOS + w) * 1280 + 256 + t];
    float m = q;
#pragma unroll
    for (int o = 16; o; o >>= 1) m = fmaxf(m, __shfl_xor_sync(0xffffffffu, m, o));
    float e = __expf(q - m);
    float s = e;
#pragma unroll
    for (int o = 16; o; o >>= 1) s += __shfl_xor_sync(0xffffffffu, s, o);
    g_Q[(size_t)w * 512 + n * 256 + t] = e / s;
}

// ---------------------------------------------------------------------------
// 6) prepB: high path, delta constants, ctx normalization (needs sums & ctx)
// ---------------------------------------------------------------------------
__global__ void k_prepB(const float* __restrict__ pool_w1, const float* __restrict__ pool_bn1,
                        const float* __restrict__ pool_w2, const float* __restrict__ pool_bn2,
                        const float* __restrict__ delta_w1, const float* __restrict__ delta_bn1,
                        const float* __restrict__ delta_w2) {
    __shared__ float sm[512], sh1[512], sh2[256], redx[256], redy[256];
    int t = threadIdx.x;   // 1 block x 512
    for (int n = 0; n < 2; n++) {
        sm[t] = g_sum[n * 512 + t] * (1.f / (float)NPOS);
        __syncthreads();
        float a1 = 0.f;
        for (int c = 0; c < 512; c++) a1 = fmaf(pool_w1[t * 512 + c], sm[c], a1);
        {
            float g = pool_bn1[t], be = pool_bn1[512 + t];
            float mm = pool_bn1[1024 + t], vv = pool_bn1[1536 + t];
            float s = g * rsqrtf(vv + BN_EPS);
            sh1[t] = a1 * s + (be - mm * s);
        }
        __syncthreads();
        float h2 = 0.f;
        if (t < 256) {
            float a2 = 0.f;
            for (int c = 0; c < 512; c++) a2 = fmaf(pool_w2[t * 512 + c], sh1[c], a2);
            float g = pool_bn2[t], be = pool_bn2[256 + t];
            float mm = pool_bn2[512 + t], vv = pool_bn2[768 + t];
            float s = g * rsqrtf(vv + BN_EPS);
            h2 = a2 * s + (be - mm * s);
        }
        __syncthreads();
        if (t < 256) { sh2[t] = h2; g_high[n * 256 + t] = h2; }
        __syncthreads();
        if (t < 256) {
            float hc = 0.f;
            for (int c = 0; c < 256; c++) hc = fmaf(delta_w1[t * 512 + 256 + c], sh2[c], hc);
            float g = delta_bn1[t], be = delta_bn1[256 + t];
            float mm = delta_bn1[512 + t], vv = delta_bn1[768 + t];
            float sd = g * rsqrtf(vv + BN_EPS);
            float td = be - mm * sd;
            float dval = sd * hc + td;
            redx[t] = delta_w2[t] * dval;
            redy[t] = delta_w2[256 + t] * dval;
        }
        __syncthreads();
        for (int st = 128; st > 0; st >>= 1) {
            if (t < st) { redx[t] += redx[t + st]; redy[t] += redy[t + st]; }
            __syncthreads();
        }
        if (t == 0) { g_cd[n * 2 + 0] = redx[0]; g_cd[n * 2 + 1] = redy[0]; }
        __syncthreads();
    }
    // normalize ctx by ksum (softmax denominator of key channel i)
    for (int idx = t; idx < 16384; idx += 512) {
        int i = (idx >> 5) & 31;
        int h = (idx >> 10) & 7;
        int n = idx >> 13;
        g_ctx[idx] /= g_ksum[n * 256 + h * 32 + i];
    }
}

// ---------------------------------------------------------------------------
// 7) Wcat[c][n*256+h*32+i] = 0.25 * sum_v wr[c][h*32+v] * ctx[n][h][i][v]
// ---------------------------------------------------------------------------
__global__ void k_wcat(const float* __restrict__ ea_wr) {
    __shared__ float sWr[256];
    int c = blockIdx.x, t = threadIdx.x;   // grid 512 x 512
    if (t < 256) sWr[t] = ea_wr[c * 256 + t];
    __syncthreads();
    int n = t >> 8, local = t & 255, h = local >> 5, i = local & 31;
    const float* cp = &g_ctx[((n * 8 + h) * 32 + i) * 32];
    float acc = 0.f;
#pragma unroll
    for (int j = 0; j < 32; j++) acc = fmaf(sWr[h * 32 + j], cp[j], acc);
    g_Wcat[c * 512 + t] = 0.25f * acc;
}

// ---------------------------------------------------------------------------
// 8) grid-sample weight per (n, position): two 256-dots + clip formula
// ---------------------------------------------------------------------------
__global__ void k_wgt() {
    __shared__ float sdx[256], sdy[256];
    int n = blockIdx.y, t = threadIdx.x;   // grid (4096,2) x 256
    if (t < 256) { sdx[t] = g_Wd[t]; sdy[t] = g_Wd[256 + t]; }
    __syncthreads();
    int warp = t >> 5, lane = t & 31;
    int w = blockIdx.x * 8 + warp;
    const float* L = &g_L2[(size_t)(n * NPOS + w) * 256];
    float ax = 0.f, ay = 0.f;
#pragma unroll
    for (int c = lane; c < 256; c += 32) {
        float v = L[c];
        ax = fmaf(sdx[c], v, ax);
        ay = fmaf(sdy[c], v, ay);
    }
#pragma unroll
    for (int o = 16; o; o >>= 1) {
        ax += __shfl_xor_sync(0xffffffffu, ax, o);
        ay += __shfl_xor_sync(0xffffffffu, ay, o);
    }
    if (lane == 0) {
        float dx = ax + g_cd[n * 2 + 0];
        float dy = ay + g_cd[n * 2 + 1];
        float gx = -1.f + (float)w * (2.f / 32767.f) + dx;
        float ix = 0.5f * gx;
        float iy = 0.5f * (-1.f + dy);
        float wx = fminf(1.f, fmaxf(0.f, 1.f - fabsf(ix)));
        float wy = fminf(1.f, fmaxf(0.f, 1.f - fabsf(iy)));
        g_wgt[n * NPOS + w] = wx * wy;
    }
}

// ---------------------------------------------------------------------------
// launcher
// ---------------------------------------------------------------------------
extern "C" void kernel_launch(void* const* d_in, const int* in_sizes, int n_in,
                              void* d_out, int out_size) {
    (void)in_sizes; (void)n_in; (void)out_size;
    const float* x         = (const float*)d_in[0];
    const float* y         = (const float*)d_in[1];
    const float* ea_wk     = (const float*)d_in[2];
    const float* ea_bk     = (const float*)d_in[3];
    const float* ea_wq     = (const float*)d_in[4];
    const float* ea_bq     = (const float*)d_in[5];
    const float* ea_wv     = (const float*)d_in[6];
    const float* ea_bv     = (const float*)d_in[7];
    const float* ea_wr     = (const float*)d_in[8];
    const float* ea_br     = (const float*)d_in[9];
    const float* pool_w1   = (const float*)d_in[10];
    const float* pool_bn1  = (const float*)d_in[11];
    const float* pool_w2   = (const float*)d_in[12];
    const float* pool_bn2  = (const float*)d_in[13];
    const float* adapt_w1  = (const float*)d_in[14];
    const float* adapt_bn1 = (const float*)d_in[15];
    const float* adapt_w2  = (const float*)d_in[16];
    const float* adapt_bn2 = (const float*)d_in[17];
    const float* delta_w1  = (const float*)d_in[18];
    const float* delta_bn1 = (const float*)d_in[19];
    const float* delta_w2  = (const float*)d_in[20];
    float* out = (float*)d_out;

    k_zero<<<64, 256>>>();
    k_prepA<<<1537, 512>>>(ea_wk, ea_bk, ea_wq, ea_bq, ea_wv, ea_bv, ea_br,
                           adapt_w1, adapt_bn1, adapt_w2, adapt_bn2,
                           delta_w1, delta_bn1, delta_w2);
    k_colmean<<<dim3(64, 2), 512>>>(x, y);
    k_gemm1<<<dim3(10, 256, 2), 256>>>(x, y);
    k_gemm2<<<dim3(2, 256, 2), 256>>>();
    k_kmax_part<<<dim3(64, 2), 256>>>();
    k_kmax_red<<<2, 256>>>();
    k_ctx<<<dim3(16, 8, 2), 256>>>();
    k_qsm<<<dim3(32768, 2), 256>>>();
    k_prepB<<<1, 512>>>(pool_w1, pool_bn1, pool_w2, pool_bn2,
                        delta_w1, delta_bn1, delta_w2);
    k_wcat<<<512, 512>>>(ea_wr);
    k_wgt<<<dim3(4096, 2), 256>>>();
    k_gemmF<<<dim3(4, 256, 1), 256>>>(x, y, out);
}

// round 6
// speedup vs baseline: 1.6790x; 1.6790x over previous
#include <cuda_runtime.h>
#include <cuda_bf16.h>
#include <cstdint>
#include <math.h>

// ---------------------------------------------------------------------------
// Problem constants
// ---------------------------------------------------------------------------
#define NPOS 32768
#define CDIM 512
#define BN_EPS 1e-5f

// ---------------------------------------------------------------------------
// Static device scratch (no allocation allowed)
// ---------------------------------------------------------------------------
__device__ float g_T   [2u * NPOS * 1280];   // per n: [keys(256) | queries(256) | values(256) | L1(512)]
__device__ float g_L2  [2u * NPOS * 256];    // adapt stage-2 output (BN folded)
__device__ float g_Q   [(size_t)NPOS * 512]; // softmaxed queries, cols = n*256 + head*32 + k
__device__ float g_Wbig[1280 * 512];         // concat weights for GEMM1 (BN folded on adapt1 rows)
__device__ float g_bias1[1280];
__device__ float g_W2  [256 * 512];          // BN-folded adapt_w2
__device__ float g_bias2[256];
__device__ float g_Wcat[512 * 512];          // 0.25 * wr @ blockdiag(ctx)  for both n
__device__ float g_brw [512];                // 0.5 * ea_br
__device__ float g_sum [1024];               // column sums of x,y (atomic)
__device__ float g_kmaxp[2 * 64 * 256];      // partial key maxes
__device__ float g_kmax[512];                // key max per (n, channel)
__device__ float g_ctx [2 * 8 * 32 * 32];    // ctx accumulators (atomic), normalized in prepB
__device__ float g_ksum[512];                // softmax denominators (atomic)
__device__ float g_high[512];                // high2 per n [2][256]
__device__ float g_Wd  [512];                // [Wdx(256) | Wdy(256)]  (delta path folded)
__device__ float g_cd  [4];                  // [cdx0, cdy0, cdx1, cdy1]
__device__ float g_wgt [2 * NPOS];           // grid_sample weight per (n, position)

// ---------------------------------------------------------------------------
// 0) zero accumulators
// ---------------------------------------------------------------------------
__global__ void k_zero() {
    int i = blockIdx.x * 256 + threadIdx.x;   // grid 64x256 = 16384
    g_ctx[i] = 0.f;
    if (i < 1024) g_sum[i] = 0.f;
    if (i < 512)  g_ksum[i] = 0.f;
}

// ---------------------------------------------------------------------------
// 1) prepA: build folded weight matrices & biases (independent of x,y)
// ---------------------------------------------------------------------------
__global__ void k_prepA(const float* __restrict__ ea_wk, const float* __restrict__ ea_bk,
                        const float* __restrict__ ea_wq, const float* __restrict__ ea_bq,
                        const float* __restrict__ ea_wv, const float* __restrict__ ea_bv,
                        const float* __restrict__ ea_br,
                        const float* __restrict__ adapt_w1, const float* __restrict__ adapt_bn1,
                        const float* __restrict__ adapt_w2, const float* __restrict__ adapt_bn2,
                        const float* __restrict__ delta_w1, const float* __restrict__ delta_bn1,
                        const float* __restrict__ delta_w2) {
    int b = blockIdx.x, t = threadIdx.x;   // 1537 blocks x 512 threads
    if (b < 1280) {
        int o = b;
        float scale = 1.f, bias = 0.f;
        const float* src;
        if (o < 256)       { src = ea_wk + o * 512;        bias = ea_bk[o]; }
        else if (o < 512)  { src = ea_wq + (o - 256) * 512; bias = ea_bq[o - 256]; }
        else if (o < 768)  { src = ea_wv + (o - 512) * 512; bias = ea_bv[o - 512]; }
        else {
            int oo = o - 768;
            float g = adapt_bn1[oo], be = adapt_bn1[512 + oo];
            float m = adapt_bn1[1024 + oo], v = adapt_bn1[1536 + oo];
            scale = g * rsqrtf(v + BN_EPS);
            bias  = be - m * scale;
            src   = adapt_w1 + oo * 512;
        }
        g_Wbig[o * 512 + t] = scale * src[t];
        if (t == 0) g_bias1[o] = bias;
    } else if (b < 1536) {
        int oo = b - 1280;
        float g = adapt_bn2[oo], be = adapt_bn2[256 + oo];
        float m = adapt_bn2[512 + oo], v = adapt_bn2[768 + oo];
        float scale = g * rsqrtf(v + BN_EPS);
        g_W2[oo * 512 + t] = scale * adapt_w2[oo * 512 + t];
        if (t == 0) g_bias2[oo] = be - m * scale;
    } else {
        g_brw[t] = 0.5f * ea_br[t];
        if (t < 256) {
            float ax = 0.f, ay = 0.f;
            for (int o = 0; o < 256; o++) {
                float g = delta_bn1[o], v = delta_bn1[768 + o];
                float sd = g * rsqrtf(v + BN_EPS);
                float wv = delta_w1[o * 512 + t];
                ax = fmaf(delta_w2[o]       * sd, wv, ax);
                ay = fmaf(delta_w2[256 + o] * sd, wv, ay);
            }
            g_Wd[t] = ax;
            g_Wd[256 + t] = ay;
        }
    }
}

// ---------------------------------------------------------------------------
// 2) column sums of x and y
// ---------------------------------------------------------------------------
__global__ void k_colmean(const float* __restrict__ x, const float* __restrict__ y) {
    int n = blockIdx.y, t = threadIdx.x;          // grid (64,2) x 512
    const float* X = n ? y : x;
    int w0 = blockIdx.x * 512;
    float acc = 0.f;
    for (int r = 0; r < 512; r++)
        acc += X[(size_t)(w0 + r) * 512 + t];
    atomicAdd(&g_sum[n * 512 + t], acc);
}

// ---------------------------------------------------------------------------
// Tensor-core GEMM: C[MxN] = A[Mx512] @ W[Nx512]^T  (split-bf16, 3-pass)
// Block tile 128x128xK32, 256 threads (8 warps), warp tile 32(m)x64(n).
// Dynamic smem layout (bf16 units), per buffer (20480 bf16 = 40960 B):
//   [0,5120)      A hi   128 rows x 40 stride (32 cols + 8 pad)
//   [5120,10240)  A lo
//   [10240,15360) B hi
//   [15360,20480) B lo
// ---------------------------------------------------------------------------
#define SMEM_STRIDE 40
#define BUF_BF16    20480
#define REG_BF16    5120

#define LDSM4(r0, r1, r2, r3, addr) \
    asm volatile("ldmatrix.sync.aligned.m8n8.x4.shared.b16 {%0,%1,%2,%3}, [%4];" \
                 : "=r"(r0), "=r"(r1), "=r"(r2), "=r"(r3) : "r"(addr))

#define MMA_BF16(c, a, b0, b1) \
    asm volatile("mma.sync.aligned.m16n8k16.row.col.f32.bf16.bf16.f32 " \
                 "{%0,%1,%2,%3}, {%4,%5,%6,%7}, {%8,%9}, {%0,%1,%2,%3};" \
                 : "+f"(c[0]), "+f"(c[1]), "+f"(c[2]), "+f"(c[3]) \
                 : "r"(a[0]), "r"(a[1]), "r"(a[2]), "r"(a[3]), "r"(b0), "r"(b1))

__device__ __forceinline__ void split_store(__nv_bfloat16* sh, __nv_bfloat16* sl, float4 v) {
    __nv_bfloat162 h01 = __floats2bfloat162_rn(v.x, v.y);
    __nv_bfloat162 h23 = __floats2bfloat162_rn(v.z, v.w);
    __nv_bfloat162 l01 = __floats2bfloat162_rn(v.x - __low2float(h01), v.y - __high2float(h01));
    __nv_bfloat162 l23 = __floats2bfloat162_rn(v.z - __low2float(h23), v.w - __high2float(h23));
    *(__nv_bfloat162*)(sh)     = h01;
    *(__nv_bfloat162*)(sh + 2) = h23;
    *(__nv_bfloat162*)(sl)     = l01;
    *(__nv_bfloat162*)(sl + 2) = l23;
}

template <int MODE>
__device__ __forceinline__ void mma_gemm(
    const float* __restrict__ A, int lda,
    const float* __restrict__ W,
    const float* __restrict__ bias,
    float* __restrict__ C, int ldc,
    const float* __restrict__ xx, const float* __restrict__ yy) {

    extern __shared__ __nv_bfloat16 s[];

    const int tid  = threadIdx.x;
    const int lane = tid & 31;
    const int w    = tid >> 5;
    const int mw   = w >> 1;          // 0..3
    const int nw   = w & 1;           // 0..1
    const int m0   = blockIdx.y * 128;
    const int n0   = blockIdx.x * 128;

    // global load assignment: 8 threads per row, float4 each; 32 rows/group, 4 groups
    const int lrow = tid >> 3;
    const int lcol = (tid & 7) * 4;
    const float* Ap = A + (size_t)(m0 + lrow) * lda + lcol;
    const float* Wp = W + (size_t)(n0 + lrow) * 512 + lcol;

    float acc[2][8][4];
#pragma unroll
    for (int mt = 0; mt < 2; mt++)
#pragma unroll
        for (int nt = 0; nt < 8; nt++)
#pragma unroll
            for (int e = 0; e < 4; e++) acc[mt][nt][e] = 0.f;

    float4 av[4], bv[4];
    // prologue: stage 0
#pragma unroll
    for (int j = 0; j < 4; j++) {
        av[j] = *(const float4*)(Ap + (size_t)j * 32 * lda);
        bv[j] = *(const float4*)(Wp + (size_t)j * 32 * 512);
    }
#pragma unroll
    for (int j = 0; j < 4; j++) {
        int r = lrow + j * 32;
        split_store(s + r * SMEM_STRIDE + lcol,
                    s + REG_BF16 + r * SMEM_STRIDE + lcol, av[j]);
        split_store(s + 2 * REG_BF16 + r * SMEM_STRIDE + lcol,
                    s + 3 * REG_BF16 + r * SMEM_STRIDE + lcol, bv[j]);
    }
    __syncthreads();

    const int krow = lane & 15;
    const int khi  = (lane >> 4) << 3;   // 0 or 8

    for (int kt = 0; kt < 16; kt++) {
        int cur = kt & 1;
        if (kt < 15) {
            int ko = (kt + 1) * 32;
#pragma unroll
            for (int j = 0; j < 4; j++) {
                av[j] = *(const float4*)(Ap + (size_t)j * 32 * lda + ko);
                bv[j] = *(const float4*)(Wp + (size_t)j * 32 * 512 + ko);
            }
        }
        uint32_t sbase = (uint32_t)__cvta_generic_to_shared(s + cur * BUF_BF16);
#pragma unroll
        for (int s16 = 0; s16 < 2; s16++) {
            int kc = s16 * 16 + khi;
            uint32_t Ah[2][4], Al[2][4], Bh[8][2], Bl[8][2];
#pragma unroll
            for (int t = 0; t < 2; t++) {
                uint32_t ad = sbase + (uint32_t)(((mw * 32 + t * 16 + krow) * SMEM_STRIDE + kc) * 2);
                LDSM4(Ah[t][0], Ah[t][1], Ah[t][2], Ah[t][3], ad);
                LDSM4(Al[t][0], Al[t][1], Al[t][2], Al[t][3], ad + REG_BF16 * 2);
            }
#pragma unroll
            for (int p = 0; p < 4; p++) {
                uint32_t bd = sbase + (uint32_t)((2 * REG_BF16 + (nw * 64 + p * 16 + krow) * SMEM_STRIDE + kc) * 2);
                uint32_t x0, x1, x2, x3;
                LDSM4(x0, x1, x2, x3, bd);
                Bh[2 * p][0] = x0; Bh[2 * p + 1][0] = x1;
                Bh[2 * p][1] = x2; Bh[2 * p + 1][1] = x3;
                LDSM4(x0, x1, x2, x3, bd + REG_BF16 * 2);
                Bl[2 * p][0] = x0; Bl[2 * p + 1][0] = x1;
                Bl[2 * p][1] = x2; Bl[2 * p + 1][1] = x3;
            }
            // pass 1: hi*hi
#pragma unroll
            for (int mt = 0; mt < 2; mt++)
#pragma unroll
                for (int nt = 0; nt < 8; nt++)
                    MMA_BF16(acc[mt][nt], Ah[mt], Bh[nt][0], Bh[nt][1]);
            // pass 2: hi*lo
#pragma unroll
            for (int mt = 0; mt < 2; mt++)
#pragma unroll
                for (int nt = 0; nt < 8; nt++)
                    MMA_BF16(acc[mt][nt], Ah[mt], Bl[nt][0], Bl[nt][1]);
            // pass 3: lo*hi
#pragma unroll
            for (int mt = 0; mt < 2; mt++)
#pragma unroll
                for (int nt = 0; nt < 8; nt++)
                    MMA_BF16(acc[mt][nt], Al[mt], Bh[nt][0], Bh[nt][1]);
        }
        if (kt < 15) {
            __nv_bfloat16* b = s + ((kt + 1) & 1) * BUF_BF16;
#pragma unroll
            for (int j = 0; j < 4; j++) {
                int r = lrow + j * 32;
                split_store(b + r * SMEM_STRIDE + lcol,
                            b + REG_BF16 + r * SMEM_STRIDE + lcol, av[j]);
                split_store(b + 2 * REG_BF16 + r * SMEM_STRIDE + lcol,
                            b + 3 * REG_BF16 + r * SMEM_STRIDE + lcol, bv[j]);
            }
            __syncthreads();
        }
    }

    // epilogue
#pragma unroll
    for (int mt = 0; mt < 2; mt++) {
        int rbase = m0 + mw * 32 + mt * 16 + (lane >> 2);
#pragma unroll
        for (int half = 0; half < 2; half++) {
            int row = rbase + half * 8;
            float wg0 = 0.f, wg1 = 0.f;
            if (MODE == 1) { wg0 = g_wgt[row]; wg1 = g_wgt[NPOS + row]; }
#pragma unroll
            for (int nt = 0; nt < 8; nt++) {
                int col = n0 + nw * 64 + nt * 8 + (lane & 3) * 2;
                float v0 = acc[mt][nt][half * 2 + 0];
                float v1 = acc[mt][nt][half * 2 + 1];
                if (MODE == 0) {
                    C[(size_t)row * ldc + col]     = v0 + bias[col];
                    C[(size_t)row * ldc + col + 1] = v1 + bias[col + 1];
                } else {
                    v0 += g_brw[col]     + 0.25f * (xx[(size_t)row * 512 + col]     + yy[(size_t)row * 512 + col]);
                    v1 += g_brw[col + 1] + 0.25f * (xx[(size_t)row * 512 + col + 1] + yy[(size_t)row * 512 + col + 1]);
                    if (col < 256) {
                        v0 += 0.25f * (g_high[col]     * wg0 + g_high[256 + col]     * wg1);
                        v1 += 0.25f * (g_high[col + 1] * wg0 + g_high[256 + col + 1] * wg1);
                    } else {
                        v0 += 0.25f * (g_L2[(size_t)row * 256 + (col - 256)] +
                                       g_L2[(size_t)(NPOS + row) * 256 + (col - 256)]);
                        v1 += 0.25f * (g_L2[(size_t)row * 256 + (col - 255)] +
                                       g_L2[(size_t)(NPOS + row) * 256 + (col - 255)]);
                    }
                    C[(size_t)row * 512 + col]     = v0;
                    C[(size_t)row * 512 + col + 1] = v1;
                }
            }
        }
    }
}

__global__ void __launch_bounds__(256) k_gemm1(const float* __restrict__ x, const float* __restrict__ y) {
    int n = blockIdx.z;
    mma_gemm<0>(n ? y : x, 512, g_Wbig, g_bias1,
                g_T + (size_t)n * NPOS * 1280, 1280, nullptr, nullptr);
}
__global__ void __launch_bounds__(256) k_gemm2() {
    int n = blockIdx.z;
    mma_gemm<0>(g_T + (size_t)n * NPOS * 1280 + 768, 1280, g_W2, g_bias2,
                g_L2 + (size_t)n * NPOS * 256, 256, nullptr, nullptr);
}
__global__ void __launch_bounds__(256) k_gemmF(const float* __restrict__ x, const float* __restrict__ y,
                                               float* __restrict__ out) {
    mma_gemm<1>(g_Q, 512, g_Wcat, nullptr, out, 512, x, y);
}

// ---------------------------------------------------------------------------
// 3) key max over positions (two-stage)
// ---------------------------------------------------------------------------
__global__ void k_kmax_part() {
    int n = blockIdx.y, t = threadIdx.x;   // grid (64,2) x 256
    int w0 = blockIdx.x * 512;
    float m = -1e30f;
    for (int r = 0; r < 512; r++)
        m = fmaxf(m, g_T[(size_t)(n * NPOS + w0 + r) * 1280 + t]);
    g_kmaxp[(size_t)(n * 64 + blockIdx.x) * 256 + t] = m;
}
__global__ void k_kmax_red() {
    int n = blockIdx.x, t = threadIdx.x;
    float m = -1e30f;
    for (int ch = 0; ch < 64; ch++)
        m = fmaxf(m, g_kmaxp[(size_t)(n * 64 + ch) * 256 + t]);
    g_kmax[n * 256 + t] = m;
}

// ---------------------------------------------------------------------------
// 4) ctx = sum_w exp(k - kmax) * v^T  (+ ksum), per (n, head)
// ---------------------------------------------------------------------------
__global__ void k_ctx() {
    int n = blockIdx.z, h = blockIdx.y;          // grid (16, 8, 2) x 256
    int w0 = blockIdx.x * 2048;
    int t = threadIdx.x;
    int p = t >> 5, i = t & 31;                  // loading role
    int ai = t >> 3, j0 = (t & 7) * 4;           // accumulation role
    float kmax = g_kmax[n * 256 + h * 32 + i];

    __shared__ float sE[8][33];
    __shared__ float sV[8][33];

    float acc0 = 0.f, acc1 = 0.f, acc2 = 0.f, acc3 = 0.f, ks = 0.f;

    for (int b = 0; b < 256; b++) {
        int w = w0 + b * 8 + p;
        size_t base = (size_t)(n * NPOS + w) * 1280;
        float e = __expf(g_T[base + h * 32 + i] - kmax);
        sE[p][i] = e;
        ks += e;
        sV[p][i] = g_T[base + 512 + h * 32 + i];
        __syncthreads();
#pragma unroll
        for (int pp = 0; pp < 8; pp++) {
            float ee = sE[pp][ai];
            acc0 = fmaf(ee, sV[pp][j0 + 0], acc0);
            acc1 = fmaf(ee, sV[pp][j0 + 1], acc1);
            acc2 = fmaf(ee, sV[pp][j0 + 2], acc2);
            acc3 = fmaf(ee, sV[pp][j0 + 3], acc3);
        }
        __syncthreads();
    }
    int base = ((n * 8 + h) * 32 + ai) * 32 + j0;
    atomicAdd(&g_ctx[base + 0], acc0);
    atomicAdd(&g_ctx[base + 1], acc1);
    atomicAdd(&g_ctx[base + 2], acc2);
    atomicAdd(&g_ctx[base + 3], acc3);
    atomicAdd(&g_ksum[n * 256 + h * 32 + i], ks);
}

// ---------------------------------------------------------------------------
// 5) query softmax over 32 head-channels (one warp = one head)
// ---------------------------------------------------------------------------
__global__ void k_qsm() {
    int w = blockIdx.x, n = blockIdx.y, t = threadIdx.x;   // grid (32768,2) x 256
    float q = g_T[(size_t)(n * NPOS + w) * 1280 + 256 + t];
    float m = q;
#pragma unroll
    for (int o = 16; o; o >>= 1) m = fmaxf(m, __shfl_xor_sync(0xffffffffu, m, o));
    float e = __expf(q - m);
    float s = e;
#pragma unroll
    for (int o = 16; o; o >>= 1) s += __shfl_xor_sync(0xffffffffu, s, o);
    g_Q[(size_t)w * 512 + n * 256 + t] = e / s;
}

// ---------------------------------------------------------------------------
// 6) prepB: high path, delta constants, ctx normalization
// ---------------------------------------------------------------------------
__global__ void k_prepB(const float* __restrict__ pool_w1, const float* __restrict__ pool_bn1,
                        const float* __restrict__ pool_w2, const float* __restrict__ pool_bn2,
                        const float* __restrict__ delta_w1, const float* __restrict__ delta_bn1,
                        const float* __restrict__ delta_w2) {
    __shared__ float sm[512], sh1[512], sh2[256], redx[256], redy[256];
    int t = threadIdx.x;   // 1 block x 512
    for (int n = 0; n < 2; n++) {
        sm[t] = g_sum[n * 512 + t] * (1.f / (float)NPOS);
        __syncthreads();
        float a1 = 0.f;
        for (int c = 0; c < 512; c++) a1 = fmaf(pool_w1[t * 512 + c], sm[c], a1);
        {
            float g = pool_bn1[t], be = pool_bn1[512 + t];
            float mm = pool_bn1[1024 + t], vv = pool_bn1[1536 + t];
            float s = g * rsqrtf(vv + BN_EPS);
            sh1[t] = a1 * s + (be - mm * s);
        }
        __syncthreads();
        float h2 = 0.f;
        if (t < 256) {
            float a2 = 0.f;
            for (int c = 0; c < 512; c++) a2 = fmaf(pool_w2[t * 512 + c], sh1[c], a2);
            float g = pool_bn2[t], be = pool_bn2[256 + t];
            float mm = pool_bn2[512 + t], vv = pool_bn2[768 + t];
            float s = g * rsqrtf(vv + BN_EPS);
            h2 = a2 * s + (be - mm * s);
        }
        __syncthreads();
        if (t < 256) { sh2[t] = h2; g_high[n * 256 + t] = h2; }
        __syncthreads();
        if (t < 256) {
            float hc = 0.f;
            for (int c = 0; c < 256; c++) hc = fmaf(delta_w1[t * 512 + 256 + c], sh2[c], hc);
            float g = delta_bn1[t], be = delta_bn1[256 + t];
            float mm = delta_bn1[512 + t], vv = delta_bn1[768 + t];
            float sd = g * rsqrtf(vv + BN_EPS);
            float td = be - mm * sd;
            float dval = sd * hc + td;
            redx[t] = delta_w2[t] * dval;
            redy[t] = delta_w2[256 + t] * dval;
        }
        __syncthreads();
        for (int st = 128; st > 0; st >>= 1) {
            if (t < st) { redx[t] += redx[t + st]; redy[t] += redy[t + st]; }
            __syncthreads();
        }
        if (t == 0) { g_cd[n * 2 + 0] = redx[0]; g_cd[n * 2 + 1] = redy[0]; }
        __syncthreads();
    }
    for (int idx = t; idx < 16384; idx += 512) {
        int i = (idx >> 5) & 31;
        int h = (idx >> 10) & 7;
        int n = idx >> 13;
        g_ctx[idx] /= g_ksum[n * 256 + h * 32 + i];
    }
}

// ---------------------------------------------------------------------------
// 7) Wcat[c][n*256+h*32+i] = 0.25 * sum_v wr[c][h*32+v] * ctx[n][h][i][v]
// ---------------------------------------------------------------------------
__global__ void k_wcat(const float* __restrict__ ea_wr) {
    __shared__ float sWr[256];
    int c = blockIdx.x, t = threadIdx.x;   // grid 512 x 512
    if (t < 256) sWr[t] = ea_wr[c * 256 + t];
    __syncthreads();
    int n = t >> 8, local = t & 255, h = local >> 5, i = local & 31;
    const float* cp = &g_ctx[((n * 8 + h) * 32 + i) * 32];
    float acc = 0.f;
#pragma unroll
    for (int j = 0; j < 32; j++) acc = fmaf(sWr[h * 32 + j], cp[j], acc);
    g_Wcat[c * 512 + t] = 0.25f * acc;
}

// ---------------------------------------------------------------------------
// 8) grid-sample weight per (n, position)
// ---------------------------------------------------------------------------
__global__ void k_wgt() {
    __shared__ float sdx[256], sdy[256];
    int n = blockIdx.y, t = threadIdx.x;   // grid (4096,2) x 256
    if (t < 256) { sdx[t] = g_Wd[t]; sdy[t] = g_Wd[256 + t]; }
    __syncthreads();
    int warp = t >> 5, lane = t & 31;
    int w = blockIdx.x * 8 + warp;
    const float* L = &g_L2[(size_t)(n * NPOS + w) * 256];
    float ax = 0.f, ay = 0.f;
#pragma unroll
    for (int c = lane; c < 256; c += 32) {
        float v = L[c];
        ax = fmaf(sdx[c], v, ax);
        ay = fmaf(sdy[c], v, ay);
    }
#pragma unroll
    for (int o = 16; o; o >>= 1) {
        ax += __shfl_xor_sync(0xffffffffu, ax, o);
        ay += __shfl_xor_sync(0xffffffffu, ay, o);
    }
    if (lane == 0) {
        float dx = ax + g_cd[n * 2 + 0];
        float dy = ay + g_cd[n * 2 + 1];
        float gx = -1.f + (float)w * (2.f / 32767.f) + dx;
        float ix = 0.5f * gx;
        float iy = 0.5f * (-1.f + dy);
        float wx = fminf(1.f, fmaxf(0.f, 1.f - fabsf(ix)));
        float wy = fminf(1.f, fmaxf(0.f, 1.f - fabsf(iy)));
        g_wgt[n * NPOS + w] = wx * wy;
    }
}

// ---------------------------------------------------------------------------
// launcher
// ---------------------------------------------------------------------------
#define GEMM_SMEM 81920

extern "C" void kernel_launch(void* const* d_in, const int* in_sizes, int n_in,
                              void* d_out, int out_size) {
    (void)in_sizes; (void)n_in; (void)out_size;
    const float* x         = (const float*)d_in[0];
    const float* y         = (const float*)d_in[1];
    const float* ea_wk     = (const float*)d_in[2];
    const float* ea_bk     = (const float*)d_in[3];
    const float* ea_wq     = (const float*)d_in[4];
    const float* ea_bq     = (const float*)d_in[5];
    const float* ea_wv     = (const float*)d_in[6];
    const float* ea_bv     = (const float*)d_in[7];
    const float* ea_wr     = (const float*)d_in[8];
    const float* ea_br     = (const float*)d_in[9];
    const float* pool_w1   = (const float*)d_in[10];
    const float* pool_bn1  = (const float*)d_in[11];
    const float* pool_w2   = (const float*)d_in[12];
    const float* pool_bn2  = (const float*)d_in[13];
    const float* adapt_w1  = (const float*)d_in[14];
    const float* adapt_bn1 = (const float*)d_in[15];
    const float* adapt_w2  = (const float*)d_in[16];
    const float* adapt_bn2 = (const float*)d_in[17];
    const float* delta_w1  = (const float*)d_in[18];
    const float* delta_bn1 = (const float*)d_in[19];
    const float* delta_w2  = (const float*)d_in[20];
    float* out = (float*)d_out;

    cudaFuncSetAttribute(k_gemm1, cudaFuncAttributeMaxDynamicSharedMemorySize, GEMM_SMEM);
    cudaFuncSetAttribute(k_gemm2, cudaFuncAttributeMaxDynamicSharedMemorySize, GEMM_SMEM);
    cudaFuncSetAttribute(k_gemmF, cudaFuncAttributeMaxDynamicSharedMemorySize, GEMM_SMEM);

    k_zero<<<64, 256>>>();
    k_prepA<<<1537, 512>>>(ea_wk, ea_bk, ea_wq, ea_bq, ea_wv, ea_bv, ea_br,
                           adapt_w1, adapt_bn1, adapt_w2, adapt_bn2,
                           delta_w1, delta_bn1, delta_w2);
    k_colmean<<<dim3(64, 2), 512>>>(x, y);
    k_gemm1<<<dim3(10, 256, 2), 256, GEMM_SMEM>>>(x, y);
    k_gemm2<<<dim3(2, 256, 2), 256, GEMM_SMEM>>>();
    k_kmax_part<<<dim3(64, 2), 256>>>();
    k_kmax_red<<<2, 256>>>();
    k_ctx<<<dim3(16, 8, 2), 256>>>();
    k_qsm<<<dim3(32768, 2), 256>>>();
    k_prepB<<<1, 512>>>(pool_w1, pool_bn1, pool_w2, pool_bn2,
                        delta_w1, delta_bn1, delta_w2);
    k_wcat<<<512, 512>>>(ea_wr);
    k_wgt<<<dim3(4096, 2), 256>>>();
    k_gemmF<<<dim3(4, 256, 1), 256, GEMM_SMEM>>>(x, y, out);
}

// round 8
// speedup vs baseline: 1.8510x; 1.1024x over previous
#include <cuda_runtime.h>
#include <cuda_bf16.h>
#include <cstdint>
#include <math.h>

// ---------------------------------------------------------------------------
// Problem constants
// ---------------------------------------------------------------------------
#define NPOS 32768
#define BN_EPS 1e-5f

// ---------------------------------------------------------------------------
// Static device scratch (no allocation allowed)
// ---------------------------------------------------------------------------
__device__ float g_KQV [2u * NPOS * 768];              // keys(256)|queries(256)|values(256)
__device__ float g_L2  [2u * NPOS * 256];              // composed adapt output
__device__ __align__(16) __nv_bfloat16 g_xh[2u * NPOS * 512];   // x,y split bf16
__device__ __align__(16) __nv_bfloat16 g_xl[2u * NPOS * 512];
__device__ __align__(16) __nv_bfloat16 g_Qh[(size_t)NPOS * 512]; // softmaxed queries split
__device__ __align__(16) __nv_bfloat16 g_Ql[(size_t)NPOS * 512];
__device__ __align__(16) __nv_bfloat16 g_Wbh[1024 * 512];  // GEMM1 weights split (KQV + W21)
__device__ __align__(16) __nv_bfloat16 g_Wbl[1024 * 512];
__device__ __align__(16) __nv_bfloat16 g_Wch[512 * 512];   // 0.25*wr@blockdiag(ctx) split
__device__ __align__(16) __nv_bfloat16 g_Wcl[512 * 512];
__device__ float g_W1f [512 * 512];          // folded adapt1 fp32 (temp)
__device__ float g_W2f [256 * 512];          // folded adapt2 fp32 (temp)
__device__ float g_b1f [512];
__device__ float g_b2f [256];
__device__ float g_bias1[1024];              // KQV biases (768) + b21 (256)
__device__ float g_brw [512];                // 0.5 * ea_br
__device__ float g_sum [1024];               // column sums of x,y (atomic)
__device__ float g_kmaxp[2 * 64 * 256];      // partial key maxes
__device__ float g_kmax[512];                // key max per (n, channel)
__device__ float g_ctx [2 * 8 * 32 * 32];    // ctx accumulators (atomic)
__device__ float g_ksum[512];                // softmax denominators (atomic)
__device__ float g_high[512];                // high2 per n [2][256]
__device__ float g_Wd  [512];                // [Wdx(256) | Wdy(256)]
__device__ float g_cd  [4];                  // [cdx0, cdy0, cdx1, cdy1]
__device__ float g_wgt [2 * NPOS];           // grid_sample weight per (n, position)

// ---------------------------------------------------------------------------
// helpers
// ---------------------------------------------------------------------------
__device__ __forceinline__ void split1(float v, __nv_bfloat16& h, __nv_bfloat16& l) {
    h = __float2bfloat16(v);
    l = __float2bfloat16(v - __bfloat162float(h));
}

// ---------------------------------------------------------------------------
// 0) zero accumulators
// ---------------------------------------------------------------------------
__global__ void k_zero() {
    int i = blockIdx.x * 256 + threadIdx.x;   // 64x256
    g_ctx[i] = 0.f;
    if (i < 1024) g_sum[i] = 0.f;
    if (i < 512)  g_ksum[i] = 0.f;
}

// ---------------------------------------------------------------------------
// 1) prepA: fold BN, split KQV weights, stage fp32 adapt weights
// ---------------------------------------------------------------------------
__global__ void k_prepA(const float* __restrict__ ea_wk, const float* __restrict__ ea_bk,
                        const float* __restrict__ ea_wq, const float* __restrict__ ea_bq,
                        const float* __restrict__ ea_wv, const float* __restrict__ ea_bv,
                        const float* __restrict__ ea_br,
                        const float* __restrict__ adapt_w1, const float* __restrict__ adapt_bn1,
                        const float* __restrict__ adapt_w2, const float* __restrict__ adapt_bn2,
                        const float* __restrict__ delta_w1, const float* __restrict__ delta_bn1,
                        const float* __restrict__ delta_w2) {
    int b = blockIdx.x, t = threadIdx.x;   // 1537 blocks x 512
    if (b < 768) {
        int o = b;
        float bias;
        const float* src;
        if (o < 256)       { src = ea_wk + o * 512;         bias = ea_bk[o]; }
        else if (o < 512)  { src = ea_wq + (o - 256) * 512; bias = ea_bq[o - 256]; }
        else               { src = ea_wv + (o - 512) * 512; bias = ea_bv[o - 512]; }
        __nv_bfloat16 h, l;
        split1(src[t], h, l);
        g_Wbh[o * 512 + t] = h;
        g_Wbl[o * 512 + t] = l;
        if (t == 0) g_bias1[o] = bias;
    } else if (b < 1280) {
        int oo = b - 768;
        float g = adapt_bn1[oo], be = adapt_bn1[512 + oo];
        float m = adapt_bn1[1024 + oo], v = adapt_bn1[1536 + oo];
        float scale = g * rsqrtf(v + BN_EPS);
        g_W1f[oo * 512 + t] = scale * adapt_w1[oo * 512 + t];
        if (t == 0) g_b1f[oo] = be - m * scale;
    } else if (b < 1536) {
        int oo = b - 1280;
        float g = adapt_bn2[oo], be = adapt_bn2[256 + oo];
        float m = adapt_bn2[512 + oo], v = adapt_bn2[768 + oo];
        float scale = g * rsqrtf(v + BN_EPS);
        g_W2f[oo * 512 + t] = scale * adapt_w2[oo * 512 + t];
        if (t == 0) g_b2f[oo] = be - m * scale;
    } else {
        g_brw[t] = 0.5f * ea_br[t];
        if (t < 256) {
            float ax = 0.f, ay = 0.f;
            for (int o = 0; o < 256; o++) {
                float g = delta_bn1[o], v = delta_bn1[768 + o];
                float sd = g * rsqrtf(v + BN_EPS);
                float wv = delta_w1[o * 512 + t];
                ax = fmaf(delta_w2[o]       * sd, wv, ax);
                ay = fmaf(delta_w2[256 + o] * sd, wv, ay);
            }
            g_Wd[t] = ax;
            g_Wd[256 + t] = ay;
        }
    }
}

// ---------------------------------------------------------------------------
// 1b) compose W21 = W2f @ W1f, b21 = W2f @ b1f + b2f; split to bf16 rows 768+
// ---------------------------------------------------------------------------
__global__ void k_compose() {
    __shared__ float s2[512];
    int b = blockIdx.x, t = threadIdx.x;   // 257 blocks x 512
    if (b < 256) {
        s2[t] = g_W2f[b * 512 + t];
        __syncthreads();
        float acc = 0.f;
        for (int j = 0; j < 512; j++)
            acc = fmaf(s2[j], g_W1f[j * 512 + t], acc);
        __nv_bfloat16 h, l;
        split1(acc, h, l);
        g_Wbh[(768 + b) * 512 + t] = h;
        g_Wbl[(768 + b) * 512 + t] = l;
    } else if (t < 256) {
        float acc = g_b2f[t];
        for (int j = 0; j < 512; j++)
            acc = fmaf(g_W2f[t * 512 + j], g_b1f[j], acc);
        g_bias1[768 + t] = acc;
    }
}

// ---------------------------------------------------------------------------
// 2) split x,y into bf16 hi/lo + column sums (fused)
// ---------------------------------------------------------------------------
__global__ void k_split(const float* __restrict__ x, const float* __restrict__ y) {
    int n = blockIdx.y, t = threadIdx.x;          // grid (64,2) x 256
    const float* X = n ? y : x;
    int w0 = blockIdx.x * 512;
    int c0 = 2 * t;
    float a0 = 0.f, a1 = 0.f;
    for (int r = 0; r < 512; r++) {
        size_t off = (size_t)(w0 + r) * 512 + c0;
        float2 v = *(const float2*)(X + off);
        a0 += v.x; a1 += v.y;
        __nv_bfloat16 h0, l0, h1, l1;
        split1(v.x, h0, l0);
        split1(v.y, h1, l1);
        size_t doff = (size_t)n * NPOS * 512 + off;
        *(__nv_bfloat162*)(g_xh + doff) = __nv_bfloat162(h0, h1);
        *(__nv_bfloat162*)(g_xl + doff) = __nv_bfloat162(l0, l1);
    }
    atomicAdd(&g_sum[n * 512 + c0],     a0);
    atomicAdd(&g_sum[n * 512 + c0 + 1], a1);
}

// ---------------------------------------------------------------------------
// Tensor-core GEMM, cp.async 4-stage pipeline, split-bf16 3-pass mma.sync.
// Tile 128x128, K-chunk 32 bf16. 256 threads, warp tile 32(m)x64(n).
// SMEM per stage: [Ahi|Alo|Bhi|Blo], each 128 rows x 80B (64B data + 16 pad)
//   = 10240 B per matrix, 40960 B per stage, 4 stages = 163840 B.
// ---------------------------------------------------------------------------
#define MATB   10240
#define STAGEB 40960
#define GEMM_SMEM 163840

#define LDSM4(r0, r1, r2, r3, addr) \
    asm volatile("ldmatrix.sync.aligned.m8n8.x4.shared.b16 {%0,%1,%2,%3}, [%4];" \
                 : "=r"(r0), "=r"(r1), "=r"(r2), "=r"(r3) : "r"(addr))

#define MMA_BF16(c, a, b0, b1) \
    asm volatile("mma.sync.aligned.m16n8k16.row.col.f32.bf16.bf16.f32 " \
                 "{%0,%1,%2,%3}, {%4,%5,%6,%7}, {%8,%9}, {%0,%1,%2,%3};" \
                 : "+f"(c[0]), "+f"(c[1]), "+f"(c[2]), "+f"(c[3]) \
                 : "r"(a[0]), "r"(a[1]), "r"(a[2]), "r"(a[3]), "r"(b0), "r"(b1))

__device__ __forceinline__ void cp16(uint32_t dst, const void* src) {
    asm volatile("cp.async.cg.shared.global [%0], [%1], 16;" :: "r"(dst), "l"(src));
}
__device__ __forceinline__ void cp_commit() {
    asm volatile("cp.async.commit_group;" ::: "memory");
}
__device__ __forceinline__ void cp_wait2() {
    asm volatile("cp.async.wait_group 2;" ::: "memory");
}

// MODE 0: gemm1' (cols<768 -> g_KQV; cols>=768 -> g_L2), +bias
// MODE 1: gemmF fused final epilogue
template <int MODE>
__device__ __forceinline__ void tc_gemm(
    const __nv_bfloat16* __restrict__ Ah, const __nv_bfloat16* __restrict__ Al,
    const __nv_bfloat16* __restrict__ Bh, const __nv_bfloat16* __restrict__ Bl,
    const float* __restrict__ bias,
    float* __restrict__ C, int n,
    const float* __restrict__ xx, const float* __restrict__ yy) {

    extern __shared__ __align__(128) char smem[];
    uint32_t sb = (uint32_t)__cvta_generic_to_shared(smem);

    const int tid  = threadIdx.x;
    const int lane = tid & 31;
    const int w    = tid >> 5;
    const int mw   = w >> 1;          // 0..3
    const int nw   = w & 1;           // 0..1
    const int m0   = blockIdx.y * 128;
    const int n0   = blockIdx.x * 128;

    // loader geometry: 512 16B-vectors per matrix, 2 per thread
    const int r0v = tid >> 2;              // row for j=0
    const int cv  = (tid & 3);             // 16B vector within 64B row

    float acc[2][8][4];
#pragma unroll
    for (int mt = 0; mt < 2; mt++)
#pragma unroll
        for (int nt = 0; nt < 8; nt++)
#pragma unroll
            for (int e = 0; e < 4; e++) acc[mt][nt][e] = 0.f;

    // --- prologue: stages 0..2 ---
#pragma unroll
    for (int s = 0; s < 3; s++) {
        int k0 = s * 32;
        uint32_t st = sb + s * STAGEB;
#pragma unroll
        for (int j = 0; j < 2; j++) {
            int row = r0v + j * 64;
            size_t ga = (size_t)(m0 + row) * 512 + k0 + cv * 8;
            size_t gb = (size_t)(n0 + row) * 512 + k0 + cv * 8;
            uint32_t so = st + row * 80 + cv * 16;
            cp16(so,            Ah + ga);
            cp16(so + MATB,     Al + ga);
            cp16(so + 2 * MATB, Bh + gb);
            cp16(so + 3 * MATB, Bl + gb);
        }
        cp_commit();
    }

    const int krow = lane & 15;
    const int khi  = (lane >> 4) << 3;   // 0 or 8 (bf16 cols)

    for (int c = 0; c < 16; c++) {
        cp_wait2();
        __syncthreads();

        // issue chunk c+3 into stage (c+3)&3 (overwrites stage consumed at c-1)
        if (c + 3 < 16) {
            int k0 = (c + 3) * 32;
            uint32_t st = sb + ((c + 3) & 3) * STAGEB;
#pragma unroll
            for (int j = 0; j < 2; j++) {
                int row = r0v + j * 64;
                size_t ga = (size_t)(m0 + row) * 512 + k0 + cv * 8;
                size_t gb = (size_t)(n0 + row) * 512 + k0 + cv * 8;
                uint32_t so = st + row * 80 + cv * 16;
                cp16(so,            Ah + ga);
                cp16(so + MATB,     Al + ga);
                cp16(so + 2 * MATB, Bh + gb);
                cp16(so + 3 * MATB, Bl + gb);
            }
        }
        cp_commit();

        uint32_t sbase = sb + (c & 3) * STAGEB;
#pragma unroll
        for (int s16 = 0; s16 < 2; s16++) {
            int kc = s16 * 16 + khi;
            uint32_t Ahf[2][4], Alf[2][4], Bhf[8][2], Blf[8][2];
#pragma unroll
            for (int t = 0; t < 2; t++) {
                uint32_t ad = sbase + (uint32_t)((mw * 32 + t * 16 + krow) * 80 + kc * 2);
                LDSM4(Ahf[t][0], Ahf[t][1], Ahf[t][2], Ahf[t][3], ad);
                LDSM4(Alf[t][0], Alf[t][1], Alf[t][2], Alf[t][3], ad + MATB);
            }
#pragma unroll
            for (int p = 0; p < 4; p++) {
                uint32_t bd = sbase + (uint32_t)(2 * MATB + (nw * 64 + p * 16 + krow) * 80 + kc * 2);
                uint32_t x0, x1, x2, x3;
                LDSM4(x0, x1, x2, x3, bd);
                Bhf[2 * p][0] = x0; Bhf[2 * p + 1][0] = x1;
                Bhf[2 * p][1] = x2; Bhf[2 * p + 1][1] = x3;
                LDSM4(x0, x1, x2, x3, bd + MATB);
                Blf[2 * p][0] = x0; Blf[2 * p + 1][0] = x1;
                Blf[2 * p][1] = x2; Blf[2 * p + 1][1] = x3;
            }
#pragma unroll
            for (int mt = 0; mt < 2; mt++)
#pragma unroll
                for (int nt = 0; nt < 8; nt++)
                    MMA_BF16(acc[mt][nt], Ahf[mt], Bhf[nt][0], Bhf[nt][1]);
#pragma unroll
            for (int mt = 0; mt < 2; mt++)
#pragma unroll
                for (int nt = 0; nt < 8; nt++)
                    MMA_BF16(acc[mt][nt], Ahf[mt], Blf[nt][0], Blf[nt][1]);
#pragma unroll
            for (int mt = 0; mt < 2; mt++)
#pragma unroll
                for (int nt = 0; nt < 8; nt++)
                    MMA_BF16(acc[mt][nt], Alf[mt], Bhf[nt][0], Bhf[nt][1]);
        }
    }

    // --- epilogue (register -> gmem) ---
#pragma unroll
    for (int mt = 0; mt < 2; mt++) {
        int rbase = m0 + mw * 32 + mt * 16 + (lane >> 2);
#pragma unroll
        for (int half = 0; half < 2; half++) {
            int row = rbase + half * 8;
            float wg0 = 0.f, wg1 = 0.f;
            if (MODE == 1) { wg0 = g_wgt[row]; wg1 = g_wgt[NPOS + row]; }
#pragma unroll
            for (int nt = 0; nt < 8; nt++) {
                int col = n0 + nw * 64 + nt * 8 + (lane & 3) * 2;
                float v0 = acc[mt][nt][half * 2 + 0];
                float v1 = acc[mt][nt][half * 2 + 1];
                if (MODE == 0) {
                    v0 += bias[col];
                    v1 += bias[col + 1];
                    if (col < 768) {
                        C[(size_t)row * 768 + col]     = v0;
                        C[(size_t)row * 768 + col + 1] = v1;
                    } else {
                        size_t o = ((size_t)n * NPOS + row) * 256 + (col - 768);
                        g_L2[o]     = v0;
                        g_L2[o + 1] = v1;
                    }
                } else {
                    v0 += g_brw[col]     + 0.25f * (xx[(size_t)row * 512 + col]     + yy[(size_t)row * 512 + col]);
                    v1 += g_brw[col + 1] + 0.25f * (xx[(size_t)row * 512 + col + 1] + yy[(size_t)row * 512 + col + 1]);
                    if (col < 256) {
                        v0 += 0.25f * (g_high[col]     * wg0 + g_high[256 + col]     * wg1);
                        v1 += 0.25f * (g_high[col + 1] * wg0 + g_high[256 + col + 1] * wg1);
                    } else {
                        v0 += 0.25f * (g_L2[(size_t)row * 256 + (col - 256)] +
                                       g_L2[(size_t)(NPOS + row) * 256 + (col - 256)]);
                        v1 += 0.25f * (g_L2[(size_t)row * 256 + (col - 255)] +
                                       g_L2[(size_t)(NPOS + row) * 256 + (col - 255)]);
                    }
                    C[(size_t)row * 512 + col]     = v0;
                    C[(size_t)row * 512 + col + 1] = v1;
                }
            }
        }
    }
}

__global__ void __launch_bounds__(256) k_gemm1() {
    int n = blockIdx.z;
    tc_gemm<0>(g_xh + (size_t)n * NPOS * 512, g_xl + (size_t)n * NPOS * 512,
               g_Wbh, g_Wbl, g_bias1,
               g_KQV + (size_t)n * NPOS * 768, n, nullptr, nullptr);
}
__global__ void __launch_bounds__(256) k_gemmF(const float* __restrict__ x,
                                               const float* __restrict__ y,
                                               float* __restrict__ out) {
    tc_gemm<1>(g_Qh, g_Ql, g_Wch, g_Wcl, nullptr, out, 0, x, y);
}

// ---------------------------------------------------------------------------
// 3) key max over positions (two-stage)
// ---------------------------------------------------------------------------
__global__ void k_kmax_part() {
    int n = blockIdx.y, t = threadIdx.x;   // grid (64,2) x 256
    int w0 = blockIdx.x * 512;
    float m = -1e30f;
    for (int r = 0; r < 512; r++)
        m = fmaxf(m, g_KQV[(size_t)(n * NPOS + w0 + r) * 768 + t]);
    g_kmaxp[(size_t)(n * 64 + blockIdx.x) * 256 + t] = m;
}
__global__ void k_kmax_red() {
    int n = blockIdx.x, t = threadIdx.x;
    float m = -1e30f;
    for (int ch = 0; ch < 64; ch++)
        m = fmaxf(m, g_kmaxp[(size_t)(n * 64 + ch) * 256 + t]);
    g_kmax[n * 256 + t] = m;
}

// ---------------------------------------------------------------------------
// 4) ctx = sum_w exp(k - kmax) * v^T  (+ ksum), per (n, head)
// ---------------------------------------------------------------------------
__global__ void k_ctx() {
    int n = blockIdx.z, h = blockIdx.y;          // grid (16, 8, 2) x 256
    int w0 = blockIdx.x * 2048;
    int t = threadIdx.x;
    int p = t >> 5, i = t & 31;                  // loading role
    int ai = t >> 3, j0 = (t & 7) * 4;           // accumulation role
    float kmax = g_kmax[n * 256 + h * 32 + i];

    __shared__ float sE[8][33];
    __shared__ float sV[8][33];

    float acc0 = 0.f, acc1 = 0.f, acc2 = 0.f, acc3 = 0.f, ks = 0.f;

    for (int b = 0; b < 256; b++) {
        int w = w0 + b * 8 + p;
        size_t base = (size_t)(n * NPOS + w) * 768;
        float e = __expf(g_KQV[base + h * 32 + i] - kmax);
        sE[p][i] = e;
        ks += e;
        sV[p][i] = g_KQV[base + 512 + h * 32 + i];
        __syncthreads();
#pragma unroll
        for (int pp = 0; pp < 8; pp++) {
            float ee = sE[pp][ai];
            acc0 = fmaf(ee, sV[pp][j0 + 0], acc0);
            acc1 = fmaf(ee, sV[pp][j0 + 1], acc1);
            acc2 = fmaf(ee, sV[pp][j0 + 2], acc2);
            acc3 = fmaf(ee, sV[pp][j0 + 3], acc3);
        }
        __syncthreads();
    }
    int base = ((n * 8 + h) * 32 + ai) * 32 + j0;
    atomicAdd(&g_ctx[base + 0], acc0);
    atomicAdd(&g_ctx[base + 1], acc1);
    atomicAdd(&g_ctx[base + 2], acc2);
    atomicAdd(&g_ctx[base + 3], acc3);
    atomicAdd(&g_ksum[n * 256 + h * 32 + i], ks);
}

// ---------------------------------------------------------------------------
// 5) query softmax -> split bf16 (warp per position, 8 heads each)
// ---------------------------------------------------------------------------
__global__ void k_qsm() {
    int n = blockIdx.y;                      // grid (4096,2) x 256
    int w = blockIdx.x * 8 + (threadIdx.x >> 5);
    int lane = threadIdx.x & 31;
    size_t base = (size_t)(n * NPOS + w) * 768 + 256;
#pragma unroll
    for (int h = 0; h < 8; h++) {
        float q = g_KQV[base + h * 32 + lane];
        float m = q;
#pragma unroll
        for (int o = 16; o; o >>= 1) m = fmaxf(m, __shfl_xor_sync(0xffffffffu, m, o));
        float e = __expf(q - m);
        float s = e;
#pragma unroll
        for (int o = 16; o; o >>= 1) s += __shfl_xor_sync(0xffffffffu, s, o);
        float v = e / s;
        __nv_bfloat16 hh, ll;
        split1(v, hh, ll);
        size_t off = (size_t)w * 512 + n * 256 + h * 32 + lane;
        g_Qh[off] = hh;
        g_Ql[off] = ll;
    }
}

// ---------------------------------------------------------------------------
// 6) prepB: high path, delta constants, ctx normalization
// ---------------------------------------------------------------------------
__global__ void k_prepB(const float* __restrict__ pool_w1, const float* __restrict__ pool_bn1,
                        const float* __restrict__ pool_w2, const float* __restrict__ pool_bn2,
                        const float* __restrict__ delta_w1, const float* __restrict__ delta_bn1,
                        const float* __restrict__ delta_w2) {
    __shared__ float sm[512], sh1[512], sh2[256], redx[256], redy[256];
    int t = threadIdx.x;   // 1 block x 512
    for (int n = 0; n < 2; n++) {
        sm[t] = g_sum[n * 512 + t] * (1.f / (float)NPOS);
        __syncthreads();
        float a1 = 0.f;
        for (int c = 0; c < 512; c++) a1 = fmaf(pool_w1[t * 512 + c], sm[c], a1);
        {
            float g = pool_bn1[t], be = pool_bn1[512 + t];
            float mm = pool_bn1[1024 + t], vv = pool_bn1[1536 + t];
            float s = g * rsqrtf(vv + BN_EPS);
            sh1[t] = a1 * s + (be - mm * s);
        }
        __syncthreads();
        float h2 = 0.f;
        if (t < 256) {
            float a2 = 0.f;
            for (int c = 0; c < 512; c++) a2 = fmaf(pool_w2[t * 512 + c], sh1[c], a2);
            float g = pool_bn2[t], be = pool_bn2[256 + t];
            float mm = pool_bn2[512 + t], vv = pool_bn2[768 + t];
            float s = g * rsqrtf(vv + BN_EPS);
            h2 = a2 * s + (be - mm * s);
        }
        __syncthreads();
        if (t < 256) { sh2[t] = h2; g_high[n * 256 + t] = h2; }
        __syncthreads();
        if (t < 256) {
            float hc = 0.f;
            for (int c = 0; c < 256; c++) hc = fmaf(delta_w1[t * 512 + 256 + c], sh2[c], hc);
            float g = delta_bn1[t], be = delta_bn1[256 + t];
            float mm = delta_bn1[512 + t], vv = delta_bn1[768 + t];
            float sd = g * rsqrtf(vv + BN_EPS);
            float td = be - mm * sd;
            float dval = sd * hc + td;
            redx[t] = delta_w2[t] * dval;
            redy[t] = delta_w2[256 + t] * dval;
        }
        __syncthreads();
        for (int st = 128; st > 0; st >>= 1) {
            if (t < st) { redx[t] += redx[t + st]; redy[t] += redy[t + st]; }
            __syncthreads();
        }
        if (t == 0) { g_cd[n * 2 + 0] = redx[0]; g_cd[n * 2 + 1] = redy[0]; }
        __syncthreads();
    }
    for (int idx = t; idx < 16384; idx += 512) {
        int i = (idx >> 5) & 31;
        int h = (idx >> 10) & 7;
        int n = idx >> 13;
        g_ctx[idx] /= g_ksum[n * 256 + h * 32 + i];
    }
}

// ---------------------------------------------------------------------------
// 7) Wcat split bf16
// ---------------------------------------------------------------------------
__global__ void k_wcat(const float* __restrict__ ea_wr) {
    __shared__ float sWr[256];
    int c = blockIdx.x, t = threadIdx.x;   // grid 512 x 512
    if (t < 256) sWr[t] = ea_wr[c * 256 + t];
    __syncthreads();
    int n = t >> 8, local = t & 255, h = local >> 5, i = local & 31;
    const float* cp = &g_ctx[((n * 8 + h) * 32 + i) * 32];
    float acc = 0.f;
#pragma unroll
    for (int j = 0; j < 32; j++) acc = fmaf(sWr[h * 32 + j], cp[j], acc);
    __nv_bfloat16 hh, ll;
    split1(0.25f * acc, hh, ll);
    g_Wch[c * 512 + t] = hh;
    g_Wcl[c * 512 + t] = ll;
}

// ---------------------------------------------------------------------------
// 8) grid-sample weight per (n, position)
// ---------------------------------------------------------------------------
__global__ void k_wgt() {
    __shared__ float sdx[256], sdy[256];
    int n = blockIdx.y, t = threadIdx.x;   // grid (4096,2) x 256
    if (t < 256) { sdx[t] = g_Wd[t]; sdy[t] = g_Wd[256 + t]; }
    __syncthreads();
    int warp = t >> 5, lane = t & 31;
    int w = blockIdx.x * 8 + warp;
    const float* L = &g_L2[(size_t)(n * NPOS + w) * 256];
    float ax = 0.f, ay = 0.f;
#pragma unroll
    for (int c = lane; c < 256; c += 32) {
        float v = L[c];
        ax = fmaf(sdx[c], v, ax);
        ay = fmaf(sdy[c], v, ay);
    }
#pragma unroll
    for (int o = 16; o; o >>= 1) {
        ax += __shfl_xor_sync(0xffffffffu, ax, o);
        ay += __shfl_xor_sync(0xffffffffu, ay, o);
    }
    if (lane == 0) {
        float dx = ax + g_cd[n * 2 + 0];
        float dy = ay + g_cd[n * 2 + 1];
        float gx = -1.f + (float)w * (2.f / 32767.f) + dx;
        float ix = 0.5f * gx;
        float iy = 0.5f * (-1.f + dy);
        float wx = fminf(1.f, fmaxf(0.f, 1.f - fabsf(ix)));
        float wy = fminf(1.f, fmaxf(0.f, 1.f - fabsf(iy)));
        g_wgt[n * NPOS + w] = wx * wy;
    }
}

// ---------------------------------------------------------------------------
// launcher
// ---------------------------------------------------------------------------
extern "C" void kernel_launch(void* const* d_in, const int* in_sizes, int n_in,
                              void* d_out, int out_size) {
    (void)in_sizes; (void)n_in; (void)out_size;
    const float* x         = (const float*)d_in[0];
    const float* y         = (const float*)d_in[1];
    const float* ea_wk     = (const float*)d_in[2];
    const float* ea_bk     = (const float*)d_in[3];
    const float* ea_wq     = (const float*)d_in[4];
    const float* ea_bq     = (const float*)d_in[5];
    const float* ea_wv     = (const float*)d_in[6];
    const float* ea_bv     = (const float*)d_in[7];
    const float* ea_wr     = (const float*)d_in[8];
    const float* ea_br     = (const float*)d_in[9];
    const float* pool_w1   = (const float*)d_in[10];
    const float* pool_bn1  = (const float*)d_in[11];
    const float* pool_w2   = (const float*)d_in[12];
    const float* pool_bn2  = (const float*)d_in[13];
    const float* adapt_w1  = (const float*)d_in[14];
    const float* adapt_bn1 = (const float*)d_in[15];
    const float* adapt_w2  = (const float*)d_in[16];
    const float* adapt_bn2 = (const float*)d_in[17];
    const float* delta_w1  = (const float*)d_in[18];
    const float* delta_bn1 = (const float*)d_in[19];
    const float* delta_w2  = (const float*)d_in[20];
    float* out = (float*)d_out;

    cudaFuncSetAttribute(k_gemm1, cudaFuncAttributeMaxDynamicSharedMemorySize, GEMM_SMEM);
    cudaFuncSetAttribute(k_gemmF, cudaFuncAttributeMaxDynamicSharedMemorySize, GEMM_SMEM);

    k_zero<<<64, 256>>>();
    k_prepA<<<1537, 512>>>(ea_wk, ea_bk, ea_wq, ea_bq, ea_wv, ea_bv, ea_br,
                           adapt_w1, adapt_bn1, adapt_w2, adapt_bn2,
                           delta_w1, delta_bn1, delta_w2);
    k_compose<<<257, 512>>>();
    k_split<<<dim3(64, 2), 256>>>(x, y);
    k_gemm1<<<dim3(8, 256, 2), 256, GEMM_SMEM>>>();
    k_kmax_part<<<dim3(64, 2), 256>>>();
    k_kmax_red<<<2, 256>>>();
    k_ctx<<<dim3(16, 8, 2), 256>>>();
    k_qsm<<<dim3(4096, 2), 256>>>();
    k_prepB<<<1, 512>>>(pool_w1, pool_bn1, pool_w2, pool_bn2,
                        delta_w1, delta_bn1, delta_w2);
    k_wcat<<<512, 512>>>(ea_wr);
    k_wgt<<<dim3(4096, 2), 256>>>();
    k_gemmF<<<dim3(4, 256, 1), 256, GEMM_SMEM>>>(x, y, out);
}

// round 9
// speedup vs baseline: 2.0291x; 1.0962x over previous
#include <cuda_runtime.h>
#include <cuda_bf16.h>
#include <cstdint>
#include <math.h>

// ---------------------------------------------------------------------------
// Problem constants
// ---------------------------------------------------------------------------
#define NPOS 32768
#define BN_EPS 1e-5f
#define KSHIFT 8.0f

// ---------------------------------------------------------------------------
// Static device scratch (no allocation allowed)
// ---------------------------------------------------------------------------
__device__ float g_KQV [2u * NPOS * 768];              // keys(256)|queries(256)|values(256)
__device__ float g_L2  [2u * NPOS * 256];              // composed adapt output
__device__ __align__(16) __nv_bfloat16 g_xh[2u * NPOS * 512];   // x,y split bf16
__device__ __align__(16) __nv_bfloat16 g_xl[2u * NPOS * 512];
__device__ __align__(16) __nv_bfloat16 g_Qh[(size_t)NPOS * 512]; // softmaxed queries split
__device__ __align__(16) __nv_bfloat16 g_Ql[(size_t)NPOS * 512];
__device__ __align__(16) __nv_bfloat16 g_Wbh[1024 * 512];  // GEMM1 weights split (KQV + W21)
__device__ __align__(16) __nv_bfloat16 g_Wbl[1024 * 512];
__device__ __align__(16) __nv_bfloat16 g_Wch[512 * 512];   // 0.25*wr@blockdiag(ctx) split
__device__ __align__(16) __nv_bfloat16 g_Wcl[512 * 512];
__device__ float g_W1f [512 * 512];          // folded adapt1 fp32 (temp)
__device__ float g_W2f [256 * 512];          // folded adapt2 fp32 (temp)
__device__ float g_b1f [512];
__device__ float g_b2f [256];
__device__ float g_bias1[1024];              // KQV biases (768) + b21 (256)
__device__ float g_brw [512];                // 0.5 * ea_br
__device__ float g_sum [1024];               // column sums of x,y (atomic)
__device__ float g_ctx [2 * 8 * 32 * 32];    // ctx accumulators (atomic)
__device__ float g_ksum[512];                // softmax denominators (atomic)
__device__ float g_high[512];                // high2 per n [2][256]
__device__ float g_Wd  [512];                // [Wdx(256) | Wdy(256)]
__device__ float g_cd  [4];                  // [cdx0, cdy0, cdx1, cdy1]
__device__ float g_wgt [2 * NPOS];           // grid_sample weight per (n, position)

// ---------------------------------------------------------------------------
// helpers
// ---------------------------------------------------------------------------
__device__ __forceinline__ void split1(float v, __nv_bfloat16& h, __nv_bfloat16& l) {
    h = __float2bfloat16(v);
    l = __float2bfloat16(v - __bfloat162float(h));
}

// ---------------------------------------------------------------------------
// 0) zero accumulators
// ---------------------------------------------------------------------------
__global__ void k_zero() {
    int i = blockIdx.x * 256 + threadIdx.x;   // 64x256
    g_ctx[i] = 0.f;
    if (i < 1024) g_sum[i] = 0.f;
    if (i < 512)  g_ksum[i] = 0.f;
}

// ---------------------------------------------------------------------------
// 1) prepA: fold BN, split KQV weights, stage fp32 adapt weights
// ---------------------------------------------------------------------------
__global__ void k_prepA(const float* __restrict__ ea_wk, const float* __restrict__ ea_bk,
                        const float* __restrict__ ea_wq, const float* __restrict__ ea_bq,
                        const float* __restrict__ ea_wv, const float* __restrict__ ea_bv,
                        const float* __restrict__ ea_br,
                        const float* __restrict__ adapt_w1, const float* __restrict__ adapt_bn1,
                        const float* __restrict__ adapt_w2, const float* __restrict__ adapt_bn2,
                        const float* __restrict__ delta_w1, const float* __restrict__ delta_bn1,
                        const float* __restrict__ delta_w2) {
    int b = blockIdx.x, t = threadIdx.x;   // 1537 blocks x 512
    if (b < 768) {
        int o = b;
        float bias;
        const float* src;
        if (o < 256)       { src = ea_wk + o * 512;         bias = ea_bk[o]; }
        else if (o < 512)  { src = ea_wq + (o - 256) * 512; bias = ea_bq[o - 256]; }
        else               { src = ea_wv + (o - 512) * 512; bias = ea_bv[o - 512]; }
        __nv_bfloat16 h, l;
        split1(src[t], h, l);
        g_Wbh[o * 512 + t] = h;
        g_Wbl[o * 512 + t] = l;
        if (t == 0) g_bias1[o] = bias;
    } else if (b < 1280) {
        int oo = b - 768;
        float g = adapt_bn1[oo], be = adapt_bn1[512 + oo];
        float m = adapt_bn1[1024 + oo], v = adapt_bn1[1536 + oo];
        float scale = g * rsqrtf(v + BN_EPS);
        g_W1f[oo * 512 + t] = scale * adapt_w1[oo * 512 + t];
        if (t == 0) g_b1f[oo] = be - m * scale;
    } else if (b < 1536) {
        int oo = b - 1280;
        float g = adapt_bn2[oo], be = adapt_bn2[256 + oo];
        float m = adapt_bn2[512 + oo], v = adapt_bn2[768 + oo];
        float scale = g * rsqrtf(v + BN_EPS);
        g_W2f[oo * 512 + t] = scale * adapt_w2[oo * 512 + t];
        if (t == 0) g_b2f[oo] = be - m * scale;
    } else {
        g_brw[t] = 0.5f * ea_br[t];
        if (t < 256) {
            float ax = 0.f, ay = 0.f;
            for (int o = 0; o < 256; o++) {
                float g = delta_bn1[o], v = delta_bn1[768 + o];
                float sd = g * rsqrtf(v + BN_EPS);
                float wv = delta_w1[o * 512 + t];
                ax = fmaf(delta_w2[o]       * sd, wv, ax);
                ay = fmaf(delta_w2[256 + o] * sd, wv, ay);
            }
            g_Wd[t] = ax;
            g_Wd[256 + t] = ay;
        }
    }
}

// ---------------------------------------------------------------------------
// 1b) compose W21 = W2f @ W1f, b21 = W2f @ b1f + b2f; split to bf16 rows 768+
// ---------------------------------------------------------------------------
__global__ void k_compose() {
    __shared__ float s2[512];
    int b = blockIdx.x, t = threadIdx.x;   // 257 blocks x 512
    if (b < 256) {
        s2[t] = g_W2f[b * 512 + t];
        __syncthreads();
        float acc = 0.f;
        for (int j = 0; j < 512; j++)
            acc = fmaf(s2[j], g_W1f[j * 512 + t], acc);
        __nv_bfloat16 h, l;
        split1(acc, h, l);
        g_Wbh[(768 + b) * 512 + t] = h;
        g_Wbl[(768 + b) * 512 + t] = l;
    } else if (t < 256) {
        float acc = g_b2f[t];
        for (int j = 0; j < 512; j++)
            acc = fmaf(g_W2f[t * 512 + j], g_b1f[j], acc);
        g_bias1[768 + t] = acc;
    }
}

// ---------------------------------------------------------------------------
// 2) split x,y into bf16 hi/lo + column sums (fused); 64 rows per block
// ---------------------------------------------------------------------------
__global__ void k_split(const float* __restrict__ x, const float* __restrict__ y) {
    int n = blockIdx.y, t = threadIdx.x;          // grid (512,2) x 256
    const float* X = n ? y : x;
    int w0 = blockIdx.x * 64;
    int c0 = 2 * t;
    float a0 = 0.f, a1 = 0.f;
    for (int r = 0; r < 64; r++) {
        size_t off = (size_t)(w0 + r) * 512 + c0;
        float2 v = *(const float2*)(X + off);
        a0 += v.x; a1 += v.y;
        __nv_bfloat16 h0, l0, h1, l1;
        split1(v.x, h0, l0);
        split1(v.y, h1, l1);
        size_t doff = (size_t)n * NPOS * 512 + off;
        *(__nv_bfloat162*)(g_xh + doff) = __nv_bfloat162(h0, h1);
        *(__nv_bfloat162*)(g_xl + doff) = __nv_bfloat162(l0, l1);
    }
    atomicAdd(&g_sum[n * 512 + c0],     a0);
    atomicAdd(&g_sum[n * 512 + c0 + 1], a1);
}

// ---------------------------------------------------------------------------
// Tensor-core GEMM, cp.async 3-stage pipeline, split-bf16 3-pass mma.sync.
// Tile 128x128, K-chunk 32 bf16. 512 threads (16 warps), warp tile 32(m)x32(n).
// SMEM per stage: [Ahi|Alo|Bhi|Blo], each 128 rows x 80B = 10240 B
//   -> 40960 B per stage, 3 stages = 122880 B.
// ---------------------------------------------------------------------------
#define MATB   10240
#define STAGEB 40960
#define GEMM_SMEM 122880

#define LDSM4(r0, r1, r2, r3, addr) \
    asm volatile("ldmatrix.sync.aligned.m8n8.x4.shared.b16 {%0,%1,%2,%3}, [%4];" \
                 : "=r"(r0), "=r"(r1), "=r"(r2), "=r"(r3) : "r"(addr))

#define MMA_BF16(c, a, b0, b1) \
    asm volatile("mma.sync.aligned.m16n8k16.row.col.f32.bf16.bf16.f32 " \
                 "{%0,%1,%2,%3}, {%4,%5,%6,%7}, {%8,%9}, {%0,%1,%2,%3};" \
                 : "+f"(c[0]), "+f"(c[1]), "+f"(c[2]), "+f"(c[3]) \
                 : "r"(a[0]), "r"(a[1]), "r"(a[2]), "r"(a[3]), "r"(b0), "r"(b1))

__device__ __forceinline__ void cp16(uint32_t dst, const void* src) {
    asm volatile("cp.async.cg.shared.global [%0], [%1], 16;" :: "r"(dst), "l"(src));
}
__device__ __forceinline__ void cp_commit() {
    asm volatile("cp.async.commit_group;" ::: "memory");
}
__device__ __forceinline__ void cp_wait1() {
    asm volatile("cp.async.wait_group 1;" ::: "memory");
}

// MODE 0: gemm1' (cols<768 -> g_KQV; cols>=768 -> g_L2), +bias
// MODE 1: gemmF fused final epilogue
template <int MODE>
__device__ __forceinline__ void tc_gemm(
    const __nv_bfloat16* __restrict__ Ah, const __nv_bfloat16* __restrict__ Al,
    const __nv_bfloat16* __restrict__ Bh, const __nv_bfloat16* __restrict__ Bl,
    const float* __restrict__ bias,
    float* __restrict__ C, int n,
    const float* __restrict__ xx, const float* __restrict__ yy) {

    extern __shared__ __align__(128) char smem[];
    uint32_t sb = (uint32_t)__cvta_generic_to_shared(smem);

    const int tid  = threadIdx.x;
    const int lane = tid & 31;
    const int w    = tid >> 5;
    const int mw   = w & 3;           // 0..3
    const int nw   = w >> 2;          // 0..3
    const int m0   = blockIdx.y * 128;
    const int n0   = blockIdx.x * 128;

    // loader geometry: 512 16B-vectors per matrix, 1 per thread per matrix
    const int lrow = tid >> 2;              // 0..127
    const int cv   = tid & 3;               // 16B vector within 64B row

    float acc[2][4][4];
#pragma unroll
    for (int mt = 0; mt < 2; mt++)
#pragma unroll
        for (int nt = 0; nt < 4; nt++)
#pragma unroll
            for (int e = 0; e < 4; e++) acc[mt][nt][e] = 0.f;

    const size_t gaBase = (size_t)(m0 + lrow) * 512 + cv * 8;
    const size_t gbBase = (size_t)(n0 + lrow) * 512 + cv * 8;
    const uint32_t soBase = lrow * 80 + cv * 16;

    // --- prologue: stages 0,1 (chunks 0,1) ---
#pragma unroll
    for (int s = 0; s < 2; s++) {
        uint32_t st = sb + s * STAGEB + soBase;
        cp16(st,            Ah + gaBase + s * 32);
        cp16(st + MATB,     Al + gaBase + s * 32);
        cp16(st + 2 * MATB, Bh + gbBase + s * 32);
        cp16(st + 3 * MATB, Bl + gbBase + s * 32);
        cp_commit();
    }

    const int krow = lane & 15;
    const int khi  = (lane >> 4) << 3;   // 0 or 8 (bf16 cols)

    for (int c = 0; c < 16; c++) {
        cp_wait1();
        __syncthreads();

        // issue chunk c+2 into stage (c+2)%3 (that stage was consumed at c-1)
        if (c + 2 < 16) {
            int k0 = (c + 2) * 32;
            uint32_t st = sb + ((c + 2) % 3) * STAGEB + soBase;
            cp16(st,            Ah + gaBase + k0);
            cp16(st + MATB,     Al + gaBase + k0);
            cp16(st + 2 * MATB, Bh + gbBase + k0);
            cp16(st + 3 * MATB, Bl + gbBase + k0);
        }
        cp_commit();

        uint32_t sbase = sb + (c % 3) * STAGEB;
#pragma unroll
        for (int s16 = 0; s16 < 2; s16++) {
            int kc = s16 * 16 + khi;
            uint32_t Ahf[2][4], Alf[2][4], Bhf[4][2], Blf[4][2];
#pragma unroll
            for (int t = 0; t < 2; t++) {
                uint32_t ad = sbase + (uint32_t)((mw * 32 + t * 16 + krow) * 80 + kc * 2);
                LDSM4(Ahf[t][0], Ahf[t][1], Ahf[t][2], Ahf[t][3], ad);
                LDSM4(Alf[t][0], Alf[t][1], Alf[t][2], Alf[t][3], ad + MATB);
            }
#pragma unroll
            for (int p = 0; p < 2; p++) {
                uint32_t bd = sbase + (uint32_t)(2 * MATB + (nw * 32 + p * 16 + krow) * 80 + kc * 2);
                uint32_t x0, x1, x2, x3;
                LDSM4(x0, x1, x2, x3, bd);
                Bhf[2 * p][0] = x0; Bhf[2 * p + 1][0] = x1;
                Bhf[2 * p][1] = x2; Bhf[2 * p + 1][1] = x3;
                LDSM4(x0, x1, x2, x3, bd + MATB);
                Blf[2 * p][0] = x0; Blf[2 * p + 1][0] = x1;
                Blf[2 * p][1] = x2; Blf[2 * p + 1][1] = x3;
            }
#pragma unroll
            for (int mt = 0; mt < 2; mt++)
#pragma unroll
                for (int nt = 0; nt < 4; nt++)
                    MMA_BF16(acc[mt][nt], Ahf[mt], Bhf[nt][0], Bhf[nt][1]);
#pragma unroll
            for (int mt = 0; mt < 2; mt++)
#pragma unroll
                for (int nt = 0; nt < 4; nt++)
                    MMA_BF16(acc[mt][nt], Ahf[mt], Blf[nt][0], Blf[nt][1]);
#pragma unroll
            for (int mt = 0; mt < 2; mt++)
#pragma unroll
                for (int nt = 0; nt < 4; nt++)
                    MMA_BF16(acc[mt][nt], Alf[mt], Bhf[nt][0], Bhf[nt][1]);
        }
    }

    // --- epilogue (register -> gmem) ---
#pragma unroll
    for (int mt = 0; mt < 2; mt++) {
        int rbase = m0 + mw * 32 + mt * 16 + (lane >> 2);
#pragma unroll
        for (int half = 0; half < 2; half++) {
            int row = rbase + half * 8;
            float wg0 = 0.f, wg1 = 0.f;
            if (MODE == 1) { wg0 = g_wgt[row]; wg1 = g_wgt[NPOS + row]; }
#pragma unroll
            for (int nt = 0; nt < 4; nt++) {
                int col = n0 + nw * 32 + nt * 8 + (lane & 3) * 2;
                float v0 = acc[mt][nt][half * 2 + 0];
                float v1 = acc[mt][nt][half * 2 + 1];
                if (MODE == 0) {
                    v0 += bias[col];
                    v1 += bias[col + 1];
                    if (col < 768) {
                        C[(size_t)row * 768 + col]     = v0;
                        C[(size_t)row * 768 + col + 1] = v1;
                    } else {
                        size_t o = ((size_t)n * NPOS + row) * 256 + (col - 768);
                        g_L2[o]     = v0;
                        g_L2[o + 1] = v1;
                    }
                } else {
                    v0 += g_brw[col]     + 0.25f * (xx[(size_t)row * 512 + col]     + yy[(size_t)row * 512 + col]);
                    v1 += g_brw[col + 1] + 0.25f * (xx[(size_t)row * 512 + col + 1] + yy[(size_t)row * 512 + col + 1]);
                    if (col < 256) {
                        v0 += 0.25f * (g_high[col]     * wg0 + g_high[256 + col]     * wg1);
                        v1 += 0.25f * (g_high[col + 1] * wg0 + g_high[256 + col + 1] * wg1);
                    } else {
                        v0 += 0.25f * (g_L2[(size_t)row * 256 + (col - 256)] +
                                       g_L2[(size_t)(NPOS + row) * 256 + (col - 256)]);
                        v1 += 0.25f * (g_L2[(size_t)row * 256 + (col - 255)] +
                                       g_L2[(size_t)(NPOS + row) * 256 + (col - 255)]);
                    }
                    C[(size_t)row * 512 + col]     = v0;
                    C[(size_t)row * 512 + col + 1] = v1;
                }
            }
        }
    }
}

__global__ void __launch_bounds__(512) k_gemm1() {
    int n = blockIdx.z;
    tc_gemm<0>(g_xh + (size_t)n * NPOS * 512, g_xl + (size_t)n * NPOS * 512,
               g_Wbh, g_Wbl, g_bias1,
               g_KQV + (size_t)n * NPOS * 768, n, nullptr, nullptr);
}
__global__ void __launch_bounds__(512) k_gemmF(const float* __restrict__ x,
                                               const float* __restrict__ y,
                                               float* __restrict__ out) {
    tc_gemm<1>(g_Qh, g_Ql, g_Wch, g_Wcl, nullptr, out, 0, x, y);
}

// ---------------------------------------------------------------------------
// 4) ctx = sum_w exp(k - KSHIFT) * v^T  (+ ksum), warp-parallel, barrier-free
//    grid (16, 8, 2) x 256 (8 warps); warp handles 256 positions of (n,h)
// ---------------------------------------------------------------------------
__global__ void k_ctx() {
    int n = blockIdx.z, h = blockIdx.y;
    int warp = threadIdx.x >> 5, lane = threadIdx.x & 31;
    int wid = blockIdx.x * 8 + warp;                    // 0..127
    size_t p0 = (size_t)wid * 256;
    const float* base = g_KQV + (size_t)n * NPOS * 768 + h * 32 + lane;

    float acc[32];
#pragma unroll
    for (int j = 0; j < 32; j++) acc[j] = 0.f;
    float ks = 0.f;

    for (int p = 0; p < 256; p += 2) {
        const float* r0 = base + (p0 + p) * 768;
        float k0 = r0[0],   v0 = r0[512];
        float k1 = r0[768], v1 = r0[1280];
        float e0 = __expf(k0 - KSHIFT);
        float e1 = __expf(k1 - KSHIFT);
        ks += e0 + e1;
#pragma unroll
        for (int j = 0; j < 32; j++) {
            acc[j] = fmaf(e0, __shfl_sync(0xffffffffu, v0, j), acc[j]);
            acc[j] = fmaf(e1, __shfl_sync(0xffffffffu, v1, j), acc[j]);
        }
    }
    int cbase = ((n * 8 + h) * 32 + lane) * 32;
#pragma unroll
    for (int j = 0; j < 32; j++)
        atomicAdd(&g_ctx[cbase + j], acc[j]);
    atomicAdd(&g_ksum[n * 256 + h * 32 + lane], ks);
}

// ---------------------------------------------------------------------------
// 5) query softmax -> split bf16 (warp per position, 8 heads each)
// ---------------------------------------------------------------------------
__global__ void k_qsm() {
    int n = blockIdx.y;                      // grid (4096,2) x 256
    int w = blockIdx.x * 8 + (threadIdx.x >> 5);
    int lane = threadIdx.x & 31;
    size_t base = (size_t)(n * NPOS + w) * 768 + 256;
#pragma unroll
    for (int h = 0; h < 8; h++) {
        float q = g_KQV[base + h * 32 + lane];
        float m = q;
#pragma unroll
        for (int o = 16; o; o >>= 1) m = fmaxf(m, __shfl_xor_sync(0xffffffffu, m, o));
        float e = __expf(q - m);
        float s = e;
#pragma unroll
        for (int o = 16; o; o >>= 1) s += __shfl_xor_sync(0xffffffffu, s, o);
        float v = e / s;
        __nv_bfloat16 hh, ll;
        split1(v, hh, ll);
        size_t off = (size_t)w * 512 + n * 256 + h * 32 + lane;
        g_Qh[off] = hh;
        g_Ql[off] = ll;
    }
}

// ---------------------------------------------------------------------------
// 6) prepB: high path, delta constants, ctx normalization
// ---------------------------------------------------------------------------
__global__ void k_prepB(const float* __restrict__ pool_w1, const float* __restrict__ pool_bn1,
                        const float* __restrict__ pool_w2, const float* __restrict__ pool_bn2,
                        const float* __restrict__ delta_w1, const float* __restrict__ delta_bn1,
                        const float* __restrict__ delta_w2) {
    __shared__ float sm[512], sh1[512], sh2[256], redx[256], redy[256];
    int t = threadIdx.x;   // 1 block x 512
    for (int n = 0; n < 2; n++) {
        sm[t] = g_sum[n * 512 + t] * (1.f / (float)NPOS);
        __syncthreads();
        float a1 = 0.f;
        for (int c = 0; c < 512; c++) a1 = fmaf(pool_w1[t * 512 + c], sm[c], a1);
        {
            float g = pool_bn1[t], be = pool_bn1[512 + t];
            float mm = pool_bn1[1024 + t], vv = pool_bn1[1536 + t];
            float s = g * rsqrtf(vv + BN_EPS);
            sh1[t] = a1 * s + (be - mm * s);
        }
        __syncthreads();
        float h2 = 0.f;
        if (t < 256) {
            float a2 = 0.f;
            for (int c = 0; c < 512; c++) a2 = fmaf(pool_w2[t * 512 + c], sh1[c], a2);
            float g = pool_bn2[t], be = pool_bn2[256 + t];
            float mm = pool_bn2[512 + t], vv = pool_bn2[768 + t];
            float s = g * rsqrtf(vv + BN_EPS);
            h2 = a2 * s + (be - mm * s);
        }
        __syncthreads();
        if (t < 256) { sh2[t] = h2; g_high[n * 256 + t] = h2; }
        __syncthreads();
        if (t < 256) {
            float hc = 0.f;
            for (int c = 0; c < 256; c++) hc = fmaf(delta_w1[t * 512 + 256 + c], sh2[c], hc);
            float g = delta_bn1[t], be = delta_bn1[256 + t];
            float mm = delta_bn1[512 + t], vv = delta_bn1[768 + t];
            float sd = g * rsqrtf(vv + BN_EPS);
            float td = be - mm * sd;
            float dval = sd * hc + td;
            redx[t] = delta_w2[t] * dval;
            redy[t] = delta_w2[256 + t] * dval;
        }
        __syncthreads();
        for (int st = 128; st > 0; st >>= 1) {
            if (t < st) { redx[t] += redx[t + st]; redy[t] += redy[t + st]; }
            __syncthreads();
        }
        if (t == 0) { g_cd[n * 2 + 0] = redx[0]; g_cd[n * 2 + 1] = redy[0]; }
        __syncthreads();
    }
    for (int idx = t; idx < 16384; idx += 512) {
        int i = (idx >> 5) & 31;
        int h = (idx >> 10) & 7;
        int n = idx >> 13;
        g_ctx[idx] /= g_ksum[n * 256 + h * 32 + i];
    }
}

// ---------------------------------------------------------------------------
// 7) Wcat split bf16
// ---------------------------------------------------------------------------
__global__ void k_wcat(const float* __restrict__ ea_wr) {
    __shared__ float sWr[256];
    int c = blockIdx.x, t = threadIdx.x;   // grid 512 x 512
    if (t < 256) sWr[t] = ea_wr[c * 256 + t];
    __syncthreads();
    int n = t >> 8, local = t & 255, h = local >> 5, i = local & 31;
    const float* cp = &g_ctx[((n * 8 + h) * 32 + i) * 32];
    float acc = 0.f;
#pragma unroll
    for (int j = 0; j < 32; j++) acc = fmaf(sWr[h * 32 + j], cp[j], acc);
    __nv_bfloat16 hh, ll;
    split1(0.25f * acc, hh, ll);
    g_Wch[c * 512 + t] = hh;
    g_Wcl[c * 512 + t] = ll;
}

// ---------------------------------------------------------------------------
// 8) grid-sample weight per (n, position)
// ---------------------------------------------------------------------------
__global__ void k_wgt() {
    __shared__ float sdx[256], sdy[256];
    int n = blockIdx.y, t = threadIdx.x;   // grid (4096,2) x 256
    if (t < 256) { sdx[t] = g_Wd[t]; sdy[t] = g_Wd[256 + t]; }
    __syncthreads();
    int warp = t >> 5, lane = t & 31;
    int w = blockIdx.x * 8 + warp;
    const float* L = &g_L2[(size_t)(n * NPOS + w) * 256];
    float ax = 0.f, ay = 0.f;
#pragma unroll
    for (int c = lane; c < 256; c += 32) {
        float v = L[c];
        ax = fmaf(sdx[c], v, ax);
        ay = fmaf(sdy[c], v, ay);
    }
#pragma unroll
    for (int o = 16; o; o >>= 1) {
        ax += __shfl_xor_sync(0xffffffffu, ax, o);
        ay += __shfl_xor_sync(0xffffffffu, ay, o);
    }
    if (lane == 0) {
        float dx = ax + g_cd[n * 2 + 0];
        float dy = ay + g_cd[n * 2 + 1];
        float gx = -1.f + (float)w * (2.f / 32767.f) + dx;
        float ix = 0.5f * gx;
        float iy = 0.5f * (-1.f + dy);
        float wx = fminf(1.f, fmaxf(0.f, 1.f - fabsf(ix)));
        float wy = fminf(1.f, fmaxf(0.f, 1.f - fabsf(iy)));
        g_wgt[n * NPOS + w] = wx * wy;
    }
}

// ---------------------------------------------------------------------------
// launcher
// ---------------------------------------------------------------------------
extern "C" void kernel_launch(void* const* d_in, const int* in_sizes, int n_in,
                              void* d_out, int out_size) {
    (void)in_sizes; (void)n_in; (void)out_size;
    const float* x         = (const float*)d_in[0];
    const float* y         = (const float*)d_in[1];
    const float* ea_wk     = (const float*)d_in[2];
    const float* ea_bk     = (const float*)d_in[3];
    const float* ea_wq     = (const float*)d_in[4];
    const float* ea_bq     = (const float*)d_in[5];
    const float* ea_wv     = (const float*)d_in[6];
    const float* ea_bv     = (const float*)d_in[7];
    const float* ea_wr     = (const float*)d_in[8];
    const float* ea_br     = (const float*)d_in[9];
    const float* pool_w1   = (const float*)d_in[10];
    const float* pool_bn1  = (const float*)d_in[11];
    const float* pool_w2   = (const float*)d_in[12];
    const float* pool_bn2  = (const float*)d_in[13];
    const float* adapt_w1  = (const float*)d_in[14];
    const float* adapt_bn1 = (const float*)d_in[15];
    const float* adapt_w2  = (const float*)d_in[16];
    const float* adapt_bn2 = (const float*)d_in[17];
    const float* delta_w1  = (const float*)d_in[18];
    const float* delta_bn1 = (const float*)d_in[19];
    const float* delta_w2  = (const float*)d_in[20];
    float* out = (float*)d_out;

    cudaFuncSetAttribute(k_gemm1, cudaFuncAttributeMaxDynamicSharedMemorySize, GEMM_SMEM);
    cudaFuncSetAttribute(k_gemmF, cudaFuncAttributeMaxDynamicSharedMemorySize, GEMM_SMEM);

    k_zero<<<64, 256>>>();
    k_prepA<<<1537, 512>>>(ea_wk, ea_bk, ea_wq, ea_bq, ea_wv, ea_bv, ea_br,
                           adapt_w1, adapt_bn1, adapt_w2, adapt_bn2,
                           delta_w1, delta_bn1, delta_w2);
    k_compose<<<257, 512>>>();
    k_split<<<dim3(512, 2), 256>>>(x, y);
    k_gemm1<<<dim3(8, 256, 2), 512, GEMM_SMEM>>>();
    k_ctx<<<dim3(16, 8, 2), 256>>>();
    k_qsm<<<dim3(4096, 2), 256>>>();
    k_prepB<<<1, 512>>>(pool_w1, pool_bn1, pool_w2, pool_bn2,
                        delta_w1, delta_bn1, delta_w2);
    k_wcat<<<512, 512>>>(ea_wr);
    k_wgt<<<dim3(4096, 2), 256>>>();
    k_gemmF<<<dim3(4, 256, 1), 512, GEMM_SMEM>>>(x, y, out);
}

// round 10
// speedup vs baseline: 2.7386x; 1.3496x over previous
#include <cuda_runtime.h>
#include <cuda_bf16.h>
#include <cstdint>
#include <math.h>

// ---------------------------------------------------------------------------
// Problem constants
// ---------------------------------------------------------------------------
#define NPOS 32768
#define BN_EPS 1e-5f
#define KSHIFT 8.0f

// ---------------------------------------------------------------------------
// Static device scratch (no allocation allowed)
// ---------------------------------------------------------------------------
__device__ float g_KQV [2u * NPOS * 768];              // keys(256)|queries(256)|values(256)
__device__ float g_L2  [2u * NPOS * 256];              // composed adapt output
__device__ __align__(16) __nv_bfloat16 g_xh[2u * NPOS * 512];   // x,y split bf16
__device__ __align__(16) __nv_bfloat16 g_xl[2u * NPOS * 512];
__device__ __align__(16) __nv_bfloat16 g_Qh[(size_t)NPOS * 512]; // softmaxed queries split
__device__ __align__(16) __nv_bfloat16 g_Ql[(size_t)NPOS * 512];
__device__ __align__(16) __nv_bfloat16 g_Wbh[1024 * 512];  // GEMM1 weights split (KQV + W21)
__device__ __align__(16) __nv_bfloat16 g_Wbl[1024 * 512];
__device__ __align__(16) __nv_bfloat16 g_Wch[512 * 512];   // 0.25*wr@blockdiag(ctx)/ksum split
__device__ __align__(16) __nv_bfloat16 g_Wcl[512 * 512];
__device__ float g_W1f [512 * 512];          // folded adapt1 fp32 (temp)
__device__ float g_W2f [256 * 512];          // folded adapt2 fp32 (temp)
__device__ float g_b1f [512];
__device__ float g_b2f [256];
__device__ float g_bias1[1024];              // KQV biases (768) + b21 (256)
__device__ float g_brw [512];                // 0.5 * ea_br
__device__ float g_sum [1024];               // column sums of x,y (atomic)
__device__ float g_sh1 [1024];               // pool stage-1 output per n
__device__ float g_ctx [2 * 8 * 32 * 32];    // ctx accumulators (atomic)
__device__ float g_ksum[512];                // softmax denominators (atomic)
__device__ float g_high[512];                // high2 per n [2][256]
__device__ float g_Wd  [512];                // [Wdx(256) | Wdy(256)]
__device__ float g_cd  [4];                  // [cdx0, cdy0, cdx1, cdy1]
__device__ float g_wgt [2 * NPOS];           // grid_sample weight per (n, position)

// ---------------------------------------------------------------------------
// helpers
// ---------------------------------------------------------------------------
__device__ __forceinline__ void split1(float v, __nv_bfloat16& h, __nv_bfloat16& l) {
    h = __float2bfloat16(v);
    l = __float2bfloat16(v - __bfloat162float(h));
}

// ---------------------------------------------------------------------------
// 0) zero accumulators
// ---------------------------------------------------------------------------
__global__ void k_zero() {
    int i = blockIdx.x * 256 + threadIdx.x;   // 64x256
    g_ctx[i] = 0.f;
    if (i < 1024) g_sum[i] = 0.f;
    if (i < 512)  g_ksum[i] = 0.f;
}

// ---------------------------------------------------------------------------
// 1) prepA: fold BN, split KQV weights, stage fp32 adapt weights
// ---------------------------------------------------------------------------
__global__ void k_prepA(const float* __restrict__ ea_wk, const float* __restrict__ ea_bk,
                        const float* __restrict__ ea_wq, const float* __restrict__ ea_bq,
                        const float* __restrict__ ea_wv, const float* __restrict__ ea_bv,
                        const float* __restrict__ ea_br,
                        const float* __restrict__ adapt_w1, const float* __restrict__ adapt_bn1,
                        const float* __restrict__ adapt_w2, const float* __restrict__ adapt_bn2,
                        const float* __restrict__ delta_w1, const float* __restrict__ delta_bn1,
                        const float* __restrict__ delta_w2) {
    int b = blockIdx.x, t = threadIdx.x;   // 1537 blocks x 512
    if (b < 768) {
        int o = b;
        float bias;
        const float* src;
        if (o < 256)       { src = ea_wk + o * 512;         bias = ea_bk[o]; }
        else if (o < 512)  { src = ea_wq + (o - 256) * 512; bias = ea_bq[o - 256]; }
        else               { src = ea_wv + (o - 512) * 512; bias = ea_bv[o - 512]; }
        __nv_bfloat16 h, l;
        split1(src[t], h, l);
        g_Wbh[o * 512 + t] = h;
        g_Wbl[o * 512 + t] = l;
        if (t == 0) g_bias1[o] = bias;
    } else if (b < 1280) {
        int oo = b - 768;
        float g = adapt_bn1[oo], be = adapt_bn1[512 + oo];
        float m = adapt_bn1[1024 + oo], v = adapt_bn1[1536 + oo];
        float scale = g * rsqrtf(v + BN_EPS);
        g_W1f[oo * 512 + t] = scale * adapt_w1[oo * 512 + t];
        if (t == 0) g_b1f[oo] = be - m * scale;
    } else if (b < 1536) {
        int oo = b - 1280;
        float g = adapt_bn2[oo], be = adapt_bn2[256 + oo];
        float m = adapt_bn2[512 + oo], v = adapt_bn2[768 + oo];
        float scale = g * rsqrtf(v + BN_EPS);
        g_W2f[oo * 512 + t] = scale * adapt_w2[oo * 512 + t];
        if (t == 0) g_b2f[oo] = be - m * scale;
    } else {
        g_brw[t] = 0.5f * ea_br[t];
        if (t < 256) {
            float ax = 0.f, ay = 0.f;
            for (int o = 0; o < 256; o++) {
                float g = delta_bn1[o], v = delta_bn1[768 + o];
                float sd = g * rsqrtf(v + BN_EPS);
                float wv = delta_w1[o * 512 + t];
                ax = fmaf(delta_w2[o]       * sd, wv, ax);
                ay = fmaf(delta_w2[256 + o] * sd, wv, ay);
            }
            g_Wd[t] = ax;
            g_Wd[256 + t] = ay;
        }
    }
}

// ---------------------------------------------------------------------------
// 1b) compose W21 = W2f @ W1f, b21 = W2f @ b1f + b2f; split to bf16 rows 768+
// ---------------------------------------------------------------------------
__global__ void k_compose() {
    __shared__ float s2[512];
    int b = blockIdx.x, t = threadIdx.x;   // 257 blocks x 512
    if (b < 256) {
        s2[t] = g_W2f[b * 512 + t];
        __syncthreads();
        float acc = 0.f;
        for (int j = 0; j < 512; j++)
            acc = fmaf(s2[j], g_W1f[j * 512 + t], acc);
        __nv_bfloat16 h, l;
        split1(acc, h, l);
        g_Wbh[(768 + b) * 512 + t] = h;
        g_Wbl[(768 + b) * 512 + t] = l;
    } else if (t < 256) {
        float acc = g_b2f[t];
        for (int j = 0; j < 512; j++)
            acc = fmaf(g_W2f[t * 512 + j], g_b1f[j], acc);
        g_bias1[768 + t] = acc;
    }
}

// ---------------------------------------------------------------------------
// 2) split x,y into bf16 hi/lo + column sums (fused); 64 rows per block
// ---------------------------------------------------------------------------
__global__ void k_split(const float* __restrict__ x, const float* __restrict__ y) {
    int n = blockIdx.y, t = threadIdx.x;          // grid (512,2) x 256
    const float* X = n ? y : x;
    int w0 = blockIdx.x * 64;
    int c0 = 2 * t;
    float a0 = 0.f, a1 = 0.f;
    for (int r = 0; r < 64; r++) {
        size_t off = (size_t)(w0 + r) * 512 + c0;
        float2 v = *(const float2*)(X + off);
        a0 += v.x; a1 += v.y;
        __nv_bfloat16 h0, l0, h1, l1;
        split1(v.x, h0, l0);
        split1(v.y, h1, l1);
        size_t doff = (size_t)n * NPOS * 512 + off;
        *(__nv_bfloat162*)(g_xh + doff) = __nv_bfloat162(h0, h1);
        *(__nv_bfloat162*)(g_xl + doff) = __nv_bfloat162(l0, l1);
    }
    atomicAdd(&g_sum[n * 512 + c0],     a0);
    atomicAdd(&g_sum[n * 512 + c0 + 1], a1);
}

// ---------------------------------------------------------------------------
// 2b) high path (parallel, warp-per-output): sh1 = BN1(pool_w1 @ mean)
// ---------------------------------------------------------------------------
__global__ void k_high1(const float* __restrict__ pool_w1, const float* __restrict__ pool_bn1) {
    int n = blockIdx.y;                     // grid (64,2) x 256
    int o = blockIdx.x * 8 + (threadIdx.x >> 5);
    int lane = threadIdx.x & 31;
    float acc = 0.f;
    for (int c = lane; c < 512; c += 32)
        acc = fmaf(pool_w1[o * 512 + c], g_sum[n * 512 + c], acc);
#pragma unroll
    for (int off = 16; off; off >>= 1) acc += __shfl_xor_sync(0xffffffffu, acc, off);
    if (lane == 0) {
        acc *= (1.f / (float)NPOS);
        float g = pool_bn1[o], be = pool_bn1[512 + o];
        float mm = pool_bn1[1024 + o], vv = pool_bn1[1536 + o];
        float s = g * rsqrtf(vv + BN_EPS);
        g_sh1[n * 512 + o] = acc * s + (be - mm * s);
    }
}

// 2c) high2 = BN2(pool_w2 @ sh1) -> g_high
__global__ void k_high2(const float* __restrict__ pool_w2, const float* __restrict__ pool_bn2) {
    int n = blockIdx.y;                     // grid (32,2) x 256
    int o = blockIdx.x * 8 + (threadIdx.x >> 5);
    int lane = threadIdx.x & 31;
    float acc = 0.f;
    for (int c = lane; c < 512; c += 32)
        acc = fmaf(pool_w2[o * 512 + c], g_sh1[n * 512 + c], acc);
#pragma unroll
    for (int off = 16; off; off >>= 1) acc += __shfl_xor_sync(0xffffffffu, acc, off);
    if (lane == 0) {
        float g = pool_bn2[o], be = pool_bn2[256 + o];
        float mm = pool_bn2[512 + o], vv = pool_bn2[768 + o];
        float s = g * rsqrtf(vv + BN_EPS);
        g_high[n * 256 + o] = acc * s + (be - mm * s);
    }
}

// 2d) delta constants from high path
__global__ void k_cd(const float* __restrict__ delta_w1, const float* __restrict__ delta_bn1,
                     const float* __restrict__ delta_w2) {
    __shared__ float sdx[256], sdy[256];
    int n = blockIdx.x;                     // grid 2 x 256
    int warp = threadIdx.x >> 5, lane = threadIdx.x & 31;
    for (int o = warp; o < 256; o += 8) {
        float acc = 0.f;
        for (int c = lane; c < 256; c += 32)
            acc = fmaf(delta_w1[o * 512 + 256 + c], g_high[n * 256 + c], acc);
#pragma unroll
        for (int off = 16; off; off >>= 1) acc += __shfl_xor_sync(0xffffffffu, acc, off);
        if (lane == 0) {
            float g = delta_bn1[o], be = delta_bn1[256 + o];
            float mm = delta_bn1[512 + o], vv = delta_bn1[768 + o];
            float sd = g * rsqrtf(vv + BN_EPS);
            float dval = acc * sd + (be - mm * sd);
            sdx[o] = delta_w2[o] * dval;
            sdy[o] = delta_w2[256 + o] * dval;
        }
    }
    __syncthreads();
    int t = threadIdx.x;
    if (t < 128) { sdx[t] += sdx[t + 128]; sdy[t] += sdy[t + 128]; }
    __syncthreads();
    for (int st = 64; st; st >>= 1) {
        if (t < st) { sdx[t] += sdx[t + st]; sdy[t] += sdy[t + st]; }
        __syncthreads();
    }
    if (t == 0) { g_cd[n * 2 + 0] = sdx[0]; g_cd[n * 2 + 1] = sdy[0]; }
}

// ---------------------------------------------------------------------------
// Tensor-core GEMM, cp.async 4-stage pipeline, split-bf16 3-pass mma.sync.
// Tile 128x128, K-chunk 32 bf16. 512 threads (16 warps), warp tile 32(m)x32(n).
// SMEM per stage: [Ahi|Alo|Bhi|Blo], each 128 rows x 80B = 10240 B
//   -> 40960 B per stage, 4 stages = 163840 B.
// ---------------------------------------------------------------------------
#define MATB   10240
#define STAGEB 40960
#define GEMM_SMEM 163840

#define LDSM4(r0, r1, r2, r3, addr) \
    asm volatile("ldmatrix.sync.aligned.m8n8.x4.shared.b16 {%0,%1,%2,%3}, [%4];" \
                 : "=r"(r0), "=r"(r1), "=r"(r2), "=r"(r3) : "r"(addr))

#define MMA_BF16(c, a, b0, b1) \
    asm volatile("mma.sync.aligned.m16n8k16.row.col.f32.bf16.bf16.f32 " \
                 "{%0,%1,%2,%3}, {%4,%5,%6,%7}, {%8,%9}, {%0,%1,%2,%3};" \
                 : "+f"(c[0]), "+f"(c[1]), "+f"(c[2]), "+f"(c[3]) \
                 : "r"(a[0]), "r"(a[1]), "r"(a[2]), "r"(a[3]), "r"(b0), "r"(b1))

__device__ __forceinline__ void cp16(uint32_t dst, const void* src) {
    asm volatile("cp.async.cg.shared.global [%0], [%1], 16;" :: "r"(dst), "l"(src));
}
__device__ __forceinline__ void cp_commit() {
    asm volatile("cp.async.commit_group;" ::: "memory");
}
__device__ __forceinline__ void cp_wait2() {
    asm volatile("cp.async.wait_group 2;" ::: "memory");
}

// MODE 0: gemm1' (cols<768 -> g_KQV; cols>=768 -> g_L2), +bias
// MODE 1: gemmF fused final epilogue
template <int MODE>
__device__ __forceinline__ void tc_gemm(
    const __nv_bfloat16* __restrict__ Ah, const __nv_bfloat16* __restrict__ Al,
    const __nv_bfloat16* __restrict__ Bh, const __nv_bfloat16* __restrict__ Bl,
    const float* __restrict__ bias,
    float* __restrict__ C, int n,
    const float* __restrict__ xx, const float* __restrict__ yy) {

    extern __shared__ __align__(128) char smem[];
    uint32_t sb = (uint32_t)__cvta_generic_to_shared(smem);

    const int tid  = threadIdx.x;
    const int lane = tid & 31;
    const int w    = tid >> 5;
    const int mw   = w & 3;           // 0..3
    const int nw   = w >> 2;          // 0..3
    const int m0   = blockIdx.y * 128;
    const int n0   = blockIdx.x * 128;

    // loader geometry: 512 16B-vectors per matrix, 1 per thread per matrix
    const int lrow = tid >> 2;              // 0..127
    const int cv   = tid & 3;               // 16B vector within 64B row

    float acc[2][4][4];
#pragma unroll
    for (int mt = 0; mt < 2; mt++)
#pragma unroll
        for (int nt = 0; nt < 4; nt++)
#pragma unroll
            for (int e = 0; e < 4; e++) acc[mt][nt][e] = 0.f;

    const size_t gaBase = (size_t)(m0 + lrow) * 512 + cv * 8;
    const size_t gbBase = (size_t)(n0 + lrow) * 512 + cv * 8;
    const uint32_t soBase = lrow * 80 + cv * 16;

    // --- prologue: stages 0..2 (chunks 0..2) ---
#pragma unroll
    for (int s = 0; s < 3; s++) {
        uint32_t st = sb + s * STAGEB + soBase;
        cp16(st,            Ah + gaBase + s * 32);
        cp16(st + MATB,     Al + gaBase + s * 32);
        cp16(st + 2 * MATB, Bh + gbBase + s * 32);
        cp16(st + 3 * MATB, Bl + gbBase + s * 32);
        cp_commit();
    }

    const int krow = lane & 15;
    const int khi  = (lane >> 4) << 3;   // 0 or 8 (bf16 cols)

    for (int c = 0; c < 16; c++) {
        cp_wait2();
        __syncthreads();

        // issue chunk c+3 into stage (c+3)&3 (that stage was consumed at c-1)
        if (c + 3 < 16) {
            int k0 = (c + 3) * 32;
            uint32_t st = sb + ((c + 3) & 3) * STAGEB + soBase;
            cp16(st,            Ah + gaBase + k0);
            cp16(st + MATB,     Al + gaBase + k0);
            cp16(st + 2 * MATB, Bh + gbBase + k0);
            cp16(st + 3 * MATB, Bl + gbBase + k0);
        }
        cp_commit();

        uint32_t sbase = sb + (c & 3) * STAGEB;
#pragma unroll
        for (int s16 = 0; s16 < 2; s16++) {
            int kc = s16 * 16 + khi;
            uint32_t Ahf[2][4], Alf[2][4], Bhf[4][2], Blf[4][2];
#pragma unroll
            for (int t = 0; t < 2; t++) {
                uint32_t ad = sbase + (uint32_t)((mw * 32 + t * 16 + krow) * 80 + kc * 2);
                LDSM4(Ahf[t][0], Ahf[t][1], Ahf[t][2], Ahf[t][3], ad);
                LDSM4(Alf[t][0], Alf[t][1], Alf[t][2], Alf[t][3], ad + MATB);
            }
#pragma unroll
            for (int p = 0; p < 2; p++) {
                uint32_t bd = sbase + (uint32_t)(2 * MATB + (nw * 32 + p * 16 + krow) * 80 + kc * 2);
                uint32_t x0, x1, x2, x3;
                LDSM4(x0, x1, x2, x3, bd);
                Bhf[2 * p][0] = x0; Bhf[2 * p + 1][0] = x1;
                Bhf[2 * p][1] = x2; Bhf[2 * p + 1][1] = x3;
                LDSM4(x0, x1, x2, x3, bd + MATB);
                Blf[2 * p][0] = x0; Blf[2 * p + 1][0] = x1;
                Blf[2 * p][1] = x2; Blf[2 * p + 1][1] = x3;
            }
#pragma unroll
            for (int mt = 0; mt < 2; mt++)
#pragma unroll
                for (int nt = 0; nt < 4; nt++)
                    MMA_BF16(acc[mt][nt], Ahf[mt], Bhf[nt][0], Bhf[nt][1]);
#pragma unroll
            for (int mt = 0; mt < 2; mt++)
#pragma unroll
                for (int nt = 0; nt < 4; nt++)
                    MMA_BF16(acc[mt][nt], Ahf[mt], Blf[nt][0], Blf[nt][1]);
#pragma unroll
            for (int mt = 0; mt < 2; mt++)
#pragma unroll
                for (int nt = 0; nt < 4; nt++)
                    MMA_BF16(acc[mt][nt], Alf[mt], Bhf[nt][0], Bhf[nt][1]);
        }
    }

    // --- epilogue (register -> gmem) ---
#pragma unroll
    for (int mt = 0; mt < 2; mt++) {
        int rbase = m0 + mw * 32 + mt * 16 + (lane >> 2);
#pragma unroll
        for (int half = 0; half < 2; half++) {
            int row = rbase + half * 8;
            float wg0 = 0.f, wg1 = 0.f;
            if (MODE == 1) { wg0 = g_wgt[row]; wg1 = g_wgt[NPOS + row]; }
#pragma unroll
            for (int nt = 0; nt < 4; nt++) {
                int col = n0 + nw * 32 + nt * 8 + (lane & 3) * 2;
                float v0 = acc[mt][nt][half * 2 + 0];
                float v1 = acc[mt][nt][half * 2 + 1];
                if (MODE == 0) {
                    v0 += bias[col];
                    v1 += bias[col + 1];
                    if (col < 768) {
                        C[(size_t)row * 768 + col]     = v0;
                        C[(size_t)row * 768 + col + 1] = v1;
                    } else {
                        size_t o = ((size_t)n * NPOS + row) * 256 + (col - 768);
                        g_L2[o]     = v0;
                        g_L2[o + 1] = v1;
                    }
                } else {
                    v0 += g_brw[col]     + 0.25f * (xx[(size_t)row * 512 + col]     + yy[(size_t)row * 512 + col]);
                    v1 += g_brw[col + 1] + 0.25f * (xx[(size_t)row * 512 + col + 1] + yy[(size_t)row * 512 + col + 1]);
                    if (col < 256) {
                        v0 += 0.25f * (g_high[col]     * wg0 + g_high[256 + col]     * wg1);
                        v1 += 0.25f * (g_high[col + 1] * wg0 + g_high[256 + col + 1] * wg1);
                    } else {
                        v0 += 0.25f * (g_L2[(size_t)row * 256 + (col - 256)] +
                                       g_L2[(size_t)(NPOS + row) * 256 + (col - 256)]);
                        v1 += 0.25f * (g_L2[(size_t)row * 256 + (col - 255)] +
                                       g_L2[(size_t)(NPOS + row) * 256 + (col - 255)]);
                    }
                    C[(size_t)row * 512 + col]     = v0;
                    C[(size_t)row * 512 + col + 1] = v1;
                }
            }
        }
    }
}

__global__ void __launch_bounds__(512) k_gemm1() {
    int n = blockIdx.z;
    tc_gemm<0>(g_xh + (size_t)n * NPOS * 512, g_xl + (size_t)n * NPOS * 512,
               g_Wbh, g_Wbl, g_bias1,
               g_KQV + (size_t)n * NPOS * 768, n, nullptr, nullptr);
}
__global__ void __launch_bounds__(512) k_gemmF(const float* __restrict__ x,
                                               const float* __restrict__ y,
                                               float* __restrict__ out) {
    tc_gemm<1>(g_Qh, g_Ql, g_Wch, g_Wcl, nullptr, out, 0, x, y);
}

// ---------------------------------------------------------------------------
// 4) fused post-GEMM kernel: ctx (blocks 0..255), qsm (256..8447), wgt (8448..16639)
// ---------------------------------------------------------------------------
__global__ void k_post() {
    int b = blockIdx.x;
    if (b < 256) {
        // --- ctx: sum_w exp(k - KSHIFT) * v^T (+ ksum), warp-parallel ---
        int n = b >> 7, h = (b >> 4) & 7, xc = b & 15;
        int warp = threadIdx.x >> 5, lane = threadIdx.x & 31;
        int wid = xc * 8 + warp;                    // 0..127
        size_t p0 = (size_t)wid * 256;
        const float* base = g_KQV + (size_t)n * NPOS * 768 + h * 32 + lane;

        float acc[32];
#pragma unroll
        for (int j = 0; j < 32; j++) acc[j] = 0.f;
        float ks = 0.f;

        for (int p = 0; p < 256; p += 2) {
            const float* r0 = base + (p0 + p) * 768;
            float k0 = r0[0],   v0 = r0[512];
            float k1 = r0[768], v1 = r0[1280];
            float e0 = __expf(k0 - KSHIFT);
            float e1 = __expf(k1 - KSHIFT);
            ks += e0 + e1;
#pragma unroll
            for (int j = 0; j < 32; j++) {
                acc[j] = fmaf(e0, __shfl_sync(0xffffffffu, v0, j), acc[j]);
                acc[j] = fmaf(e1, __shfl_sync(0xffffffffu, v1, j), acc[j]);
            }
        }
        int cbase = ((n * 8 + h) * 32 + lane) * 32;
#pragma unroll
        for (int j = 0; j < 32; j++)
            atomicAdd(&g_ctx[cbase + j], acc[j]);
        atomicAdd(&g_ksum[n * 256 + h * 32 + lane], ks);
    } else if (b < 8448) {
        // --- qsm: query softmax -> split bf16 (warp per position) ---
        int idx = b - 256;
        int n = idx >> 12;
        int wpos = (idx & 4095) * 8 + (threadIdx.x >> 5);
        int lane = threadIdx.x & 31;
        size_t base = (size_t)(n * NPOS + wpos) * 768 + 256;
#pragma unroll
        for (int h = 0; h < 8; h++) {
            float q = g_KQV[base + h * 32 + lane];
            float m = q;
#pragma unroll
            for (int o = 16; o; o >>= 1) m = fmaxf(m, __shfl_xor_sync(0xffffffffu, m, o));
            float e = __expf(q - m);
            float s = e;
#pragma unroll
            for (int o = 16; o; o >>= 1) s += __shfl_xor_sync(0xffffffffu, s, o);
            float v = e / s;
            __nv_bfloat16 hh, ll;
            split1(v, hh, ll);
            size_t off = (size_t)wpos * 512 + n * 256 + h * 32 + lane;
            g_Qh[off] = hh;
            g_Ql[off] = ll;
        }
    } else {
        // --- wgt: grid-sample weight per (n, position) ---
        __shared__ float sdx[256], sdy[256];
        int idx = b - 8448;
        int n = idx >> 12;
        int t = threadIdx.x;
        if (t < 256) { sdx[t] = g_Wd[t]; sdy[t] = g_Wd[256 + t]; }
        __syncthreads();
        int warp = t >> 5, lane = t & 31;
        int wpos = (idx & 4095) * 8 + warp;
        const float* L = &g_L2[(size_t)(n * NPOS + wpos) * 256];
        float ax = 0.f, ay = 0.f;
#pragma unroll
        for (int c = lane; c < 256; c += 32) {
            float v = L[c];
            ax = fmaf(sdx[c], v, ax);
            ay = fmaf(sdy[c], v, ay);
        }
#pragma unroll
        for (int o = 16; o; o >>= 1) {
            ax += __shfl_xor_sync(0xffffffffu, ax, o);
            ay += __shfl_xor_sync(0xffffffffu, ay, o);
        }
        if (lane == 0) {
            float dx = ax + g_cd[n * 2 + 0];
            float dy = ay + g_cd[n * 2 + 1];
            float gx = -1.f + (float)wpos * (2.f / 32767.f) + dx;
            float ix = 0.5f * gx;
            float iy = 0.5f * (-1.f + dy);
            float wx = fminf(1.f, fmaxf(0.f, 1.f - fabsf(ix)));
            float wy = fminf(1.f, fmaxf(0.f, 1.f - fabsf(iy)));
            g_wgt[n * NPOS + wpos] = wx * wy;
        }
    }
}

// ---------------------------------------------------------------------------
// 7) Wcat split bf16 (ksum normalization folded in)
// ---------------------------------------------------------------------------
__global__ void k_wcat(const float* __restrict__ ea_wr) {
    __shared__ float sWr[256];
    int c = blockIdx.x, t = threadIdx.x;   // grid 512 x 512
    if (t < 256) sWr[t] = ea_wr[c * 256 + t];
    __syncthreads();
    int n = t >> 8, local = t & 255, h = local >> 5, i = local & 31;
    const float* cp = &g_ctx[((n * 8 + h) * 32 + i) * 32];
    float acc = 0.f;
#pragma unroll
    for (int j = 0; j < 32; j++) acc = fmaf(sWr[h * 32 + j], cp[j], acc);
    float ks = g_ksum[n * 256 + h * 32 + i];
    __nv_bfloat16 hh, ll;
    split1(0.25f * acc / ks, hh, ll);
    g_Wch[c * 512 + t] = hh;
    g_Wcl[c * 512 + t] = ll;
}

// ---------------------------------------------------------------------------
// launcher
// ---------------------------------------------------------------------------
extern "C" void kernel_launch(void* const* d_in, const int* in_sizes, int n_in,
                              void* d_out, int out_size) {
    (void)in_sizes; (void)n_in; (void)out_size;
    const float* x         = (const float*)d_in[0];
    const float* y         = (const float*)d_in[1];
    const float* ea_wk     = (const float*)d_in[2];
    const float* ea_bk     = (const float*)d_in[3];
    const float* ea_wq     = (const float*)d_in[4];
    const float* ea_bq     = (const float*)d_in[5];
    const float* ea_wv     = (const float*)d_in[6];
    const float* ea_bv     = (const float*)d_in[7];
    const float* ea_wr     = (const float*)d_in[8];
    const float* ea_br     = (const float*)d_in[9];
    const float* pool_w1   = (const float*)d_in[10];
    const float* pool_bn1  = (const float*)d_in[11];
    const float* pool_w2   = (const float*)d_in[12];
    const float* pool_bn2  = (const float*)d_in[13];
    const float* adapt_w1  = (const float*)d_in[14];
    const float* adapt_bn1 = (const float*)d_in[15];
    const float* adapt_w2  = (const float*)d_in[16];
    const float* adapt_bn2 = (const float*)d_in[17];
    const float* delta_w1  = (const float*)d_in[18];
    const float* delta_bn1 = (const float*)d_in[19];
    const float* delta_w2  = (const float*)d_in[20];
    float* out = (float*)d_out;

    cudaFuncSetAttribute(k_gemm1, cudaFuncAttributeMaxDynamicSharedMemorySize, GEMM_SMEM);
    cudaFuncSetAttribute(k_gemmF, cudaFuncAttributeMaxDynamicSharedMemorySize, GEMM_SMEM);

    k_zero<<<64, 256>>>();
    k_prepA<<<1537, 512>>>(ea_wk, ea_bk, ea_wq, ea_bq, ea_wv, ea_bv, ea_br,
                           adapt_w1, adapt_bn1, adapt_w2, adapt_bn2,
                           delta_w1, delta_bn1, delta_w2);
    k_compose<<<257, 512>>>();
    k_split<<<dim3(512, 2), 256>>>(x, y);
    k_high1<<<dim3(64, 2), 256>>>(pool_w1, pool_bn1);
    k_high2<<<dim3(32, 2), 256>>>(pool_w2, pool_bn2);
    k_cd<<<2, 256>>>(delta_w1, delta_bn1, delta_w2);
    k_gemm1<<<dim3(8, 256, 2), 512, GEMM_SMEM>>>();
    k_post<<<16640, 256>>>();
    k_wcat<<<512, 512>>>(ea_wr);
    k_gemmF<<<dim3(4, 256, 1), 512, GEMM_SMEM>>>(x, y, out);
}

// round 11
// speedup vs baseline: 3.4757x; 1.2692x over previous
#include <cuda_runtime.h>
#include <cuda_bf16.h>
#include <cuda_fp16.h>
#include <cstdint>
#include <math.h>

// ---------------------------------------------------------------------------
// Problem constants
// ---------------------------------------------------------------------------
#define NPOS 32768
#define BN_EPS 1e-5f
#define KSHIFT 8.0f

// ---------------------------------------------------------------------------
// Static device scratch (no allocation allowed)
// ---------------------------------------------------------------------------
__device__ float g_KQV [2u * NPOS * 768];              // keys(256)|queries(256)|values(256)
__device__ float g_L2  [2u * NPOS * 256];              // composed adapt output
__device__ __align__(16) __half g_xh[2u * NPOS * 512];   // x,y fp16
__device__ __align__(16) __half g_Qh[(size_t)NPOS * 512]; // softmaxed queries fp16
__device__ __align__(16) __half g_Wbh[1024 * 512];  // GEMM1 weights hi (KQV + W21)
__device__ __align__(16) __half g_Wbl[1024 * 512];  // GEMM1 weights lo
__device__ __align__(16) __half g_Wch[512 * 512];   // 0.25*wr@blockdiag(ctx)/ksum hi
__device__ __align__(16) __half g_Wcl[512 * 512];   // lo
__device__ float g_W1f [512 * 512];          // folded adapt1 fp32 (temp)
__device__ float g_W2f [256 * 512];          // folded adapt2 fp32 (temp)
__device__ float g_b1f [512];
__device__ float g_b2f [256];
__device__ float g_bias1[1024];              // KQV biases (768) + b21 (256)
__device__ float g_brw [512];                // 0.5 * ea_br
__device__ float g_sum [1024];               // column sums of x,y (atomic)
__device__ float g_sh1 [1024];               // pool stage-1 output per n
__device__ float g_ctx [2 * 8 * 32 * 32];    // ctx accumulators (atomic)
__device__ float g_ksum[512];                // softmax denominators (atomic)
__device__ float g_high[512];                // high2 per n [2][256]
__device__ float g_Wd  [512];                // [Wdx(256) | Wdy(256)]
__device__ float g_cd  [4];                  // [cdx0, cdy0, cdx1, cdy1]
__device__ float g_wgt [2 * NPOS];           // grid_sample weight per (n, position)

// ---------------------------------------------------------------------------
// helpers
// ---------------------------------------------------------------------------
__device__ __forceinline__ void split1h(float v, __half& h, __half& l) {
    h = __float2half_rn(v);
    l = __float2half_rn(v - __half2float(h));
}

// ---------------------------------------------------------------------------
// 0) zero accumulators
// ---------------------------------------------------------------------------
__global__ void k_zero() {
    int i = blockIdx.x * 256 + threadIdx.x;   // 64x256
    g_ctx[i] = 0.f;
    if (i < 1024) g_sum[i] = 0.f;
    if (i < 512)  g_ksum[i] = 0.f;
}

// ---------------------------------------------------------------------------
// 1) prepA: fold BN, split KQV weights (fp16 hi/lo), stage fp32 adapt weights
// ---------------------------------------------------------------------------
__global__ void k_prepA(const float* __restrict__ ea_wk, const float* __restrict__ ea_bk,
                        const float* __restrict__ ea_wq, const float* __restrict__ ea_bq,
                        const float* __restrict__ ea_wv, const float* __restrict__ ea_bv,
                        const float* __restrict__ ea_br,
                        const float* __restrict__ adapt_w1, const float* __restrict__ adapt_bn1,
                        const float* __restrict__ adapt_w2, const float* __restrict__ adapt_bn2,
                        const float* __restrict__ delta_w1, const float* __restrict__ delta_bn1,
                        const float* __restrict__ delta_w2) {
    int b = blockIdx.x, t = threadIdx.x;   // 1537 blocks x 512
    if (b < 768) {
        int o = b;
        float bias;
        const float* src;
        if (o < 256)       { src = ea_wk + o * 512;         bias = ea_bk[o]; }
        else if (o < 512)  { src = ea_wq + (o - 256) * 512; bias = ea_bq[o - 256]; }
        else               { src = ea_wv + (o - 512) * 512; bias = ea_bv[o - 512]; }
        __half h, l;
        split1h(src[t], h, l);
        g_Wbh[o * 512 + t] = h;
        g_Wbl[o * 512 + t] = l;
        if (t == 0) g_bias1[o] = bias;
    } else if (b < 1280) {
        int oo = b - 768;
        float g = adapt_bn1[oo], be = adapt_bn1[512 + oo];
        float m = adapt_bn1[1024 + oo], v = adapt_bn1[1536 + oo];
        float scale = g * rsqrtf(v + BN_EPS);
        g_W1f[oo * 512 + t] = scale * adapt_w1[oo * 512 + t];
        if (t == 0) g_b1f[oo] = be - m * scale;
    } else if (b < 1536) {
        int oo = b - 1280;
        float g = adapt_bn2[oo], be = adapt_bn2[256 + oo];
        float m = adapt_bn2[512 + oo], v = adapt_bn2[768 + oo];
        float scale = g * rsqrtf(v + BN_EPS);
        g_W2f[oo * 512 + t] = scale * adapt_w2[oo * 512 + t];
        if (t == 0) g_b2f[oo] = be - m * scale;
    } else {
        g_brw[t] = 0.5f * ea_br[t];
        if (t < 256) {
            float ax = 0.f, ay = 0.f;
            for (int o = 0; o < 256; o++) {
                float g = delta_bn1[o], v = delta_bn1[768 + o];
                float sd = g * rsqrtf(v + BN_EPS);
                float wv = delta_w1[o * 512 + t];
                ax = fmaf(delta_w2[o]       * sd, wv, ax);
                ay = fmaf(delta_w2[256 + o] * sd, wv, ay);
            }
            g_Wd[t] = ax;
            g_Wd[256 + t] = ay;
        }
    }
}

// ---------------------------------------------------------------------------
// 1b) compose W21 = W2f @ W1f, b21 = W2f @ b1f + b2f; fp16 split rows 768+
// ---------------------------------------------------------------------------
__global__ void k_compose() {
    __shared__ float s2[512];
    int b = blockIdx.x, t = threadIdx.x;   // 257 blocks x 512
    if (b < 256) {
        s2[t] = g_W2f[b * 512 + t];
        __syncthreads();
        float acc = 0.f;
        for (int j = 0; j < 512; j++)
            acc = fmaf(s2[j], g_W1f[j * 512 + t], acc);
        __half h, l;
        split1h(acc, h, l);
        g_Wbh[(768 + b) * 512 + t] = h;
        g_Wbl[(768 + b) * 512 + t] = l;
    } else if (t < 256) {
        float acc = g_b2f[t];
        for (int j = 0; j < 512; j++)
            acc = fmaf(g_W2f[t * 512 + j], g_b1f[j], acc);
        g_bias1[768 + t] = acc;
    }
}

// ---------------------------------------------------------------------------
// 2) convert x,y to fp16 + column sums (fused); 64 rows per block
// ---------------------------------------------------------------------------
__global__ void k_split(const float* __restrict__ x, const float* __restrict__ y) {
    int n = blockIdx.y, t = threadIdx.x;          // grid (512,2) x 256
    const float* X = n ? y : x;
    int w0 = blockIdx.x * 64;
    int c0 = 2 * t;
    float a0 = 0.f, a1 = 0.f;
    for (int r = 0; r < 64; r++) {
        size_t off = (size_t)(w0 + r) * 512 + c0;
        float2 v = *(const float2*)(X + off);
        a0 += v.x; a1 += v.y;
        *(__half2*)(g_xh + (size_t)n * NPOS * 512 + off) = __floats2half2_rn(v.x, v.y);
    }
    atomicAdd(&g_sum[n * 512 + c0],     a0);
    atomicAdd(&g_sum[n * 512 + c0 + 1], a1);
}

// ---------------------------------------------------------------------------
// 2b) high path (parallel, warp-per-output): sh1 = BN1(pool_w1 @ mean)
// ---------------------------------------------------------------------------
__global__ void k_high1(const float* __restrict__ pool_w1, const float* __restrict__ pool_bn1) {
    int n = blockIdx.y;                     // grid (64,2) x 256
    int o = blockIdx.x * 8 + (threadIdx.x >> 5);
    int lane = threadIdx.x & 31;
    float acc = 0.f;
    for (int c = lane; c < 512; c += 32)
        acc = fmaf(pool_w1[o * 512 + c], g_sum[n * 512 + c], acc);
#pragma unroll
    for (int off = 16; off; off >>= 1) acc += __shfl_xor_sync(0xffffffffu, acc, off);
    if (lane == 0) {
        acc *= (1.f / (float)NPOS);
        float g = pool_bn1[o], be = pool_bn1[512 + o];
        float mm = pool_bn1[1024 + o], vv = pool_bn1[1536 + o];
        float s = g * rsqrtf(vv + BN_EPS);
        g_sh1[n * 512 + o] = acc * s + (be - mm * s);
    }
}

// 2c) high2 = BN2(pool_w2 @ sh1) -> g_high
__global__ void k_high2(const float* __restrict__ pool_w2, const float* __restrict__ pool_bn2) {
    int n = blockIdx.y;                     // grid (32,2) x 256
    int o = blockIdx.x * 8 + (threadIdx.x >> 5);
    int lane = threadIdx.x & 31;
    float acc = 0.f;
    for (int c = lane; c < 512; c += 32)
        acc = fmaf(pool_w2[o * 512 + c], g_sh1[n * 512 + c], acc);
#pragma unroll
    for (int off = 16; off; off >>= 1) acc += __shfl_xor_sync(0xffffffffu, acc, off);
    if (lane == 0) {
        float g = pool_bn2[o], be = pool_bn2[256 + o];
        float mm = pool_bn2[512 + o], vv = pool_bn2[768 + o];
        float s = g * rsqrtf(vv + BN_EPS);
        g_high[n * 256 + o] = acc * s + (be - mm * s);
    }
}

// 2d) delta constants from high path
__global__ void k_cd(const float* __restrict__ delta_w1, const float* __restrict__ delta_bn1,
                     const float* __restrict__ delta_w2) {
    __shared__ float sdx[256], sdy[256];
    int n = blockIdx.x;                     // grid 2 x 256
    int warp = threadIdx.x >> 5, lane = threadIdx.x & 31;
    for (int o = warp; o < 256; o += 8) {
        float acc = 0.f;
        for (int c = lane; c < 256; c += 32)
            acc = fmaf(delta_w1[o * 512 + 256 + c], g_high[n * 256 + c], acc);
#pragma unroll
        for (int off = 16; off; off >>= 1) acc += __shfl_xor_sync(0xffffffffu, acc, off);
        if (lane == 0) {
            float g = delta_bn1[o], be = delta_bn1[256 + o];
            float mm = delta_bn1[512 + o], vv = delta_bn1[768 + o];
            float sd = g * rsqrtf(vv + BN_EPS);
            float dval = acc * sd + (be - mm * sd);
            sdx[o] = delta_w2[o] * dval;
            sdy[o] = delta_w2[256 + o] * dval;
        }
    }
    __syncthreads();
    int t = threadIdx.x;
    if (t < 128) { sdx[t] += sdx[t + 128]; sdy[t] += sdy[t + 128]; }
    __syncthreads();
    for (int st = 64; st; st >>= 1) {
        if (t < st) { sdx[t] += sdx[t + st]; sdy[t] += sdy[t + st]; }
        __syncthreads();
    }
    if (t == 0) { g_cd[n * 2 + 0] = sdx[0]; g_cd[n * 2 + 1] = sdy[0]; }
}

// ---------------------------------------------------------------------------
// Tensor-core GEMM, fp16 2-pass (A single, W hi/lo), cp.async 3-stage.
// Tile 128x128, K-chunk 64 fp16. 512 threads (16 warps), warp tile 32x32.
// SMEM per stage: [A|Bhi|Blo], each 128 rows x 144B (128B data + 16 pad)
//   = 18432 B per matrix, 55296 B per stage, 3 stages = 165888 B.
// ---------------------------------------------------------------------------
#define MATB   18432
#define STAGEB 55296
#define GEMM_SMEM 165888

#define LDSM4(r0, r1, r2, r3, addr) \
    asm volatile("ldmatrix.sync.aligned.m8n8.x4.shared.b16 {%0,%1,%2,%3}, [%4];" \
                 : "=r"(r0), "=r"(r1), "=r"(r2), "=r"(r3) : "r"(addr))

#define MMA_F16(c, a, b0, b1) \
    asm volatile("mma.sync.aligned.m16n8k16.row.col.f32.f16.f16.f32 " \
                 "{%0,%1,%2,%3}, {%4,%5,%6,%7}, {%8,%9}, {%0,%1,%2,%3};" \
                 : "+f"(c[0]), "+f"(c[1]), "+f"(c[2]), "+f"(c[3]) \
                 : "r"(a[0]), "r"(a[1]), "r"(a[2]), "r"(a[3]), "r"(b0), "r"(b1))

__device__ __forceinline__ void cp16(uint32_t dst, const void* src) {
    asm volatile("cp.async.cg.shared.global [%0], [%1], 16;" :: "r"(dst), "l"(src));
}
__device__ __forceinline__ void cp_commit() {
    asm volatile("cp.async.commit_group;" ::: "memory");
}
__device__ __forceinline__ void cp_wait1() {
    asm volatile("cp.async.wait_group 1;" ::: "memory");
}

// MODE 0: gemm1' (cols<768 -> g_KQV; cols>=768 -> g_L2), +bias
// MODE 1: gemmF fused final epilogue
template <int MODE>
__device__ __forceinline__ void tc_gemm(
    const __half* __restrict__ Ax,
    const __half* __restrict__ Bh, const __half* __restrict__ Bl,
    const float* __restrict__ bias,
    float* __restrict__ C, int n,
    const float* __restrict__ xx, const float* __restrict__ yy) {

    extern __shared__ __align__(128) char smem[];
    uint32_t sb = (uint32_t)__cvta_generic_to_shared(smem);

    const int tid  = threadIdx.x;
    const int lane = tid & 31;
    const int w    = tid >> 5;
    const int mw   = w & 3;           // 0..3
    const int nw   = w >> 2;          // 0..3
    const int m0   = blockIdx.y * 128;
    const int n0   = blockIdx.x * 128;

    // loader geometry: 8 threads per 128B row; each thread 2 rows per matrix
    const int lrow = tid >> 3;              // 0..63
    const int cv   = tid & 7;               // 16B vector within 128B row

    float acc[2][4][4];
#pragma unroll
    for (int mt = 0; mt < 2; mt++)
#pragma unroll
        for (int nt = 0; nt < 4; nt++)
#pragma unroll
            for (int e = 0; e < 4; e++) acc[mt][nt][e] = 0.f;

    const size_t gaBase = (size_t)(m0 + lrow) * 512 + cv * 8;
    const size_t gbBase = (size_t)(n0 + lrow) * 512 + cv * 8;
    const uint32_t soBase = lrow * 144 + cv * 16;
    const size_t rowStepG = (size_t)64 * 512;
    const uint32_t rowStepS = 64 * 144;

    // --- prologue: stages 0,1 (chunks 0,1) ---
#pragma unroll
    for (int s = 0; s < 2; s++) {
        int k0 = s * 64;
        uint32_t st = sb + s * STAGEB + soBase;
#pragma unroll
        for (int j = 0; j < 2; j++) {
            cp16(st + j * rowStepS,            Ax + gaBase + j * rowStepG + k0);
            cp16(st + MATB + j * rowStepS,     Bh + gbBase + j * rowStepG + k0);
            cp16(st + 2 * MATB + j * rowStepS, Bl + gbBase + j * rowStepG + k0);
        }
        cp_commit();
    }

    const int krow = lane & 15;
    const int khi  = (lane >> 4) << 3;   // 0 or 8 (fp16 cols)

    for (int c = 0; c < 8; c++) {
        cp_wait1();
        __syncthreads();

        // issue chunk c+2 into stage (c+2)%3 (consumed at iteration c-1)
        if (c + 2 < 8) {
            int k0 = (c + 2) * 64;
            uint32_t st = sb + ((c + 2) % 3) * STAGEB + soBase;
#pragma unroll
            for (int j = 0; j < 2; j++) {
                cp16(st + j * rowStepS,            Ax + gaBase + j * rowStepG + k0);
                cp16(st + MATB + j * rowStepS,     Bh + gbBase + j * rowStepG + k0);
                cp16(st + 2 * MATB + j * rowStepS, Bl + gbBase + j * rowStepG + k0);
            }
        }
        cp_commit();

        uint32_t sbase = sb + (c % 3) * STAGEB;
#pragma unroll
        for (int s16 = 0; s16 < 4; s16++) {
            int kc = s16 * 16 + khi;     // fp16 element offset within chunk
            uint32_t Af[2][4], Bhf[4][2], Blf[4][2];
#pragma unroll
            for (int t = 0; t < 2; t++) {
                uint32_t ad = sbase + (uint32_t)((mw * 32 + t * 16 + krow) * 144 + kc * 2);
                LDSM4(Af[t][0], Af[t][1], Af[t][2], Af[t][3], ad);
            }
#pragma unroll
            for (int p = 0; p < 2; p++) {
                uint32_t bd = sbase + (uint32_t)(MATB + (nw * 32 + p * 16 + krow) * 144 + kc * 2);
                uint32_t x0, x1, x2, x3;
                LDSM4(x0, x1, x2, x3, bd);
                Bhf[2 * p][0] = x0; Bhf[2 * p + 1][0] = x1;
                Bhf[2 * p][1] = x2; Bhf[2 * p + 1][1] = x3;
                LDSM4(x0, x1, x2, x3, bd + MATB);
                Blf[2 * p][0] = x0; Blf[2 * p + 1][0] = x1;
                Blf[2 * p][1] = x2; Blf[2 * p + 1][1] = x3;
            }
#pragma unroll
            for (int mt = 0; mt < 2; mt++)
#pragma unroll
                for (int nt = 0; nt < 4; nt++)
                    MMA_F16(acc[mt][nt], Af[mt], Bhf[nt][0], Bhf[nt][1]);
#pragma unroll
            for (int mt = 0; mt < 2; mt++)
#pragma unroll
                for (int nt = 0; nt < 4; nt++)
                    MMA_F16(acc[mt][nt], Af[mt], Blf[nt][0], Blf[nt][1]);
        }
    }

    // --- epilogue (register -> gmem) ---
#pragma unroll
    for (int mt = 0; mt < 2; mt++) {
        int rbase = m0 + mw * 32 + mt * 16 + (lane >> 2);
#pragma unroll
        for (int half = 0; half < 2; half++) {
            int row = rbase + half * 8;
            float wg0 = 0.f, wg1 = 0.f;
            if (MODE == 1) { wg0 = g_wgt[row]; wg1 = g_wgt[NPOS + row]; }
#pragma unroll
            for (int nt = 0; nt < 4; nt++) {
                int col = n0 + nw * 32 + nt * 8 + (lane & 3) * 2;
                float v0 = acc[mt][nt][half * 2 + 0];
                float v1 = acc[mt][nt][half * 2 + 1];
                if (MODE == 0) {
                    v0 += bias[col];
                    v1 += bias[col + 1];
                    if (col < 768) {
                        C[(size_t)row * 768 + col]     = v0;
                        C[(size_t)row * 768 + col + 1] = v1;
                    } else {
                        size_t o = ((size_t)n * NPOS + row) * 256 + (col - 768);
                        g_L2[o]     = v0;
                        g_L2[o + 1] = v1;
                    }
                } else {
                    v0 += g_brw[col]     + 0.25f * (xx[(size_t)row * 512 + col]     + yy[(size_t)row * 512 + col]);
                    v1 += g_brw[col + 1] + 0.25f * (xx[(size_t)row * 512 + col + 1] + yy[(size_t)row * 512 + col + 1]);
                    if (col < 256) {
                        v0 += 0.25f * (g_high[col]     * wg0 + g_high[256 + col]     * wg1);
                        v1 += 0.25f * (g_high[col + 1] * wg0 + g_high[256 + col + 1] * wg1);
                    } else {
                        v0 += 0.25f * (g_L2[(size_t)row * 256 + (col - 256)] +
                                       g_L2[(size_t)(NPOS + row) * 256 + (col - 256)]);
                        v1 += 0.25f * (g_L2[(size_t)row * 256 + (col - 255)] +
                                       g_L2[(size_t)(NPOS + row) * 256 + (col - 255)]);
                    }
                    C[(size_t)row * 512 + col]     = v0;
                    C[(size_t)row * 512 + col + 1] = v1;
                }
            }
        }
    }
}

__global__ void __launch_bounds__(512) k_gemm1() {
    int n = blockIdx.z;
    tc_gemm<0>(g_xh + (size_t)n * NPOS * 512,
               g_Wbh, g_Wbl, g_bias1,
               g_KQV + (size_t)n * NPOS * 768, n, nullptr, nullptr);
}
__global__ void __launch_bounds__(512) k_gemmF(const float* __restrict__ x,
                                               const float* __restrict__ y,
                                               float* __restrict__ out) {
    tc_gemm<1>(g_Qh, g_Wch, g_Wcl, nullptr, out, 0, x, y);
}

// ---------------------------------------------------------------------------
// 4) fused post-GEMM kernel: ctx (blocks 0..255), qsm (256..8447), wgt (8448..16639)
// ---------------------------------------------------------------------------
__global__ void k_post() {
    int b = blockIdx.x;
    if (b < 256) {
        // --- ctx: sum_w exp(k - KSHIFT) * v^T (+ ksum), warp-parallel ---
        int n = b >> 7, h = (b >> 4) & 7, xc = b & 15;
        int warp = threadIdx.x >> 5, lane = threadIdx.x & 31;
        int wid = xc * 8 + warp;                    // 0..127
        size_t p0 = (size_t)wid * 256;
        const float* base = g_KQV + (size_t)n * NPOS * 768 + h * 32 + lane;

        float acc[32];
#pragma unroll
        for (int j = 0; j < 32; j++) acc[j] = 0.f;
        float ks = 0.f;

        for (int p = 0; p < 256; p += 2) {
            const float* r0 = base + (p0 + p) * 768;
            float k0 = r0[0],   v0 = r0[512];
            float k1 = r0[768], v1 = r0[1280];
            float e0 = __expf(k0 - KSHIFT);
            float e1 = __expf(k1 - KSHIFT);
            ks += e0 + e1;
#pragma unroll
            for (int j = 0; j < 32; j++) {
                acc[j] = fmaf(e0, __shfl_sync(0xffffffffu, v0, j), acc[j]);
                acc[j] = fmaf(e1, __shfl_sync(0xffffffffu, v1, j), acc[j]);
            }
        }
        int cbase = ((n * 8 + h) * 32 + lane) * 32;
#pragma unroll
        for (int j = 0; j < 32; j++)
            atomicAdd(&g_ctx[cbase + j], acc[j]);
        atomicAdd(&g_ksum[n * 256 + h * 32 + lane], ks);
    } else if (b < 8448) {
        // --- qsm: query softmax -> fp16 (warp per position) ---
        int idx = b - 256;
        int n = idx >> 12;
        int wpos = (idx & 4095) * 8 + (threadIdx.x >> 5);
        int lane = threadIdx.x & 31;
        size_t base = (size_t)(n * NPOS + wpos) * 768 + 256;
#pragma unroll
        for (int h = 0; h < 8; h++) {
            float q = g_KQV[base + h * 32 + lane];
            float m = q;
#pragma unroll
            for (int o = 16; o; o >>= 1) m = fmaxf(m, __shfl_xor_sync(0xffffffffu, m, o));
            float e = __expf(q - m);
            float s = e;
#pragma unroll
            for (int o = 16; o; o >>= 1) s += __shfl_xor_sync(0xffffffffu, s, o);
            g_Qh[(size_t)wpos * 512 + n * 256 + h * 32 + lane] = __float2half_rn(e / s);
        }
    } else {
        // --- wgt: grid-sample weight per (n, position) ---
        __shared__ float sdx[256], sdy[256];
        int idx = b - 8448;
        int n = idx >> 12;
        int t = threadIdx.x;
        if (t < 256) { sdx[t] = g_Wd[t]; sdy[t] = g_Wd[256 + t]; }
        __syncthreads();
        int warp = t >> 5, lane = t & 31;
        int wpos = (idx & 4095) * 8 + warp;
        const float* L = &g_L2[(size_t)(n * NPOS + wpos) * 256];
        float ax = 0.f, ay = 0.f;
#pragma unroll
        for (int c = lane; c < 256; c += 32) {
            float v = L[c];
            ax = fmaf(sdx[c], v, ax);
            ay = fmaf(sdy[c], v, ay);
        }
#pragma unroll
        for (int o = 16; o; o >>= 1) {
            ax += __shfl_xor_sync(0xffffffffu, ax, o);
            ay += __shfl_xor_sync(0xffffffffu, ay, o);
        }
        if (lane == 0) {
            float dx = ax + g_cd[n * 2 + 0];
            float dy = ay + g_cd[n * 2 + 1];
            float gx = -1.f + (float)wpos * (2.f / 32767.f) + dx;
            float ix = 0.5f * gx;
            float iy = 0.5f * (-1.f + dy);
            float wx = fminf(1.f, fmaxf(0.f, 1.f - fabsf(ix)));
            float wy = fminf(1.f, fmaxf(0.f, 1.f - fabsf(iy)));
            g_wgt[n * NPOS + wpos] = wx * wy;
        }
    }
}

// ---------------------------------------------------------------------------
// 7) Wcat fp16 hi/lo (ksum normalization folded in)
// ---------------------------------------------------------------------------
__global__ void k_wcat(const float* __restrict__ ea_wr) {
    __shared__ float sWr[256];
    int c = blockIdx.x, t = threadIdx.x;   // grid 512 x 512
    if (t < 256) sWr[t] = ea_wr[c * 256 + t];
    __syncthreads();
    int n = t >> 8, local = t & 255, h = local >> 5, i = local & 31;
    const float* cp = &g_ctx[((n * 8 + h) * 32 + i) * 32];
    float acc = 0.f;
#pragma unroll
    for (int j = 0; j < 32; j++) acc = fmaf(sWr[h * 32 + j], cp[j], acc);
    float ks = g_ksum[n * 256 + h * 32 + i];
    __half hh, ll;
    split1h(0.25f * acc / ks, hh, ll);
    g_Wch[c * 512 + t] = hh;
    g_Wcl[c * 512 + t] = ll;
}

// ---------------------------------------------------------------------------
// launcher
// ---------------------------------------------------------------------------
extern "C" void kernel_launch(void* const* d_in, const int* in_sizes, int n_in,
                              void* d_out, int out_size) {
    (void)in_sizes; (void)n_in; (void)out_size;
    const float* x         = (const float*)d_in[0];
    const float* y         = (const float*)d_in[1];
    const float* ea_wk     = (const float*)d_in[2];
    const float* ea_bk     = (const float*)d_in[3];
    const float* ea_wq     = (const float*)d_in[4];
    const float* ea_bq     = (const float*)d_in[5];
    const float* ea_wv     = (const float*)d_in[6];
    const float* ea_bv     = (const float*)d_in[7];
    const float* ea_wr     = (const float*)d_in[8];
    const float* ea_br     = (const float*)d_in[9];
    const float* pool_w1   = (const float*)d_in[10];
    const float* pool_bn1  = (const float*)d_in[11];
    const float* pool_w2   = (const float*)d_in[12];
    const float* pool_bn2  = (const float*)d_in[13];
    const float* adapt_w1  = (const float*)d_in[14];
    const float* adapt_bn1 = (const float*)d_in[15];
    const float* adapt_w2  = (const float*)d_in[16];
    const float* adapt_bn2 = (const float*)d_in[17];
    const float* delta_w1  = (const float*)d_in[18];
    const float* delta_bn1 = (const float*)d_in[19];
    const float* delta_w2  = (const float*)d_in[20];
    float* out = (float*)d_out;

    cudaFuncSetAttribute(k_gemm1, cudaFuncAttributeMaxDynamicSharedMemorySize, GEMM_SMEM);
    cudaFuncSetAttribute(k_gemmF, cudaFuncAttributeMaxDynamicSharedMemorySize, GEMM_SMEM);

    k_zero<<<64, 256>>>();
    k_prepA<<<1537, 512>>>(ea_wk, ea_bk, ea_wq, ea_bq, ea_wv, ea_bv, ea_br,
                           adapt_w1, adapt_bn1, adapt_w2, adapt_bn2,
                           delta_w1, delta_bn1, delta_w2);
    k_compose<<<257, 512>>>();
    k_split<<<dim3(512, 2), 256>>>(x, y);
    k_high1<<<dim3(64, 2), 256>>>(pool_w1, pool_bn1);
    k_high2<<<dim3(32, 2), 256>>>(pool_w2, pool_bn2);
    k_cd<<<2, 256>>>(delta_w1, delta_bn1, delta_w2);
    k_gemm1<<<dim3(8, 256, 2), 512, GEMM_SMEM>>>();
    k_post<<<16640, 256>>>();
    k_wcat<<<512, 512>>>(ea_wr);
    k_gemmF<<<dim3(4, 256, 1), 512, GEMM_SMEM>>>(x, y, out);
}